// round 1
// baseline (speedup 1.0000x reference)
#include <cuda_runtime.h>
#include <cstdint>
#include <cstddef>

#define N_B 2
#define L_S 2048
#define E_D 1024
#define H_N 16
#define D_H 64
#define QS  68          // padded shared stride (floats) for Qts/Kts/Vs
#define L2E 1.44269504088896341f

// -------- scratch (no allocations allowed; device globals are the sanctioned path) --------
__device__ float g_q [N_B*H_N*L_S*D_H];   // [n][h][l][d]
__device__ float g_k [N_B*H_N*L_S*D_H];
__device__ float g_v [N_B*H_N*L_S*D_H];
__device__ float g_ao[N_B*L_S*E_D];       // attention output, [n*L+l][E]

// ============================================================================
// Kernel 1: fused QKV projection.  y[n,h,l,d] = sum_e x[n,l,h,e] * W[d,e]
// Input rows (n,l,h) are contiguous (ri*64+e). Block: 64 rows, 256 threads.
// Each thread owns one output column d and 16 rows; W row lives in registers.
// ============================================================================
__global__ __launch_bounds__(256) void proj_kernel(
    const float* __restrict__ vals, const float* __restrict__ keys,
    const float* __restrict__ qry,
    const float* __restrict__ Wv, const float* __restrict__ Wk,
    const float* __restrict__ Wq)
{
    const float* X; const float* W; float* Y;
    int which = blockIdx.y;
    if (which == 0)      { X = vals; W = Wv; Y = g_v; }
    else if (which == 1) { X = keys; W = Wk; Y = g_k; }
    else                 { X = qry;  W = Wq; Y = g_q; }

    __shared__ float Xs[64*64];
    int rowBase = blockIdx.x * 64;

    const float4* Xg  = (const float4*)(X + (size_t)rowBase * 64);
    float4*       Xs4 = (float4*)Xs;
    for (int i = threadIdx.x; i < 1024; i += 256) Xs4[i] = Xg[i];

    int d  = threadIdx.x & 63;
    int rq = threadIdx.x >> 6;

    float w[64];
    const float4* Wg = (const float4*)(W + d * 64);
    #pragma unroll
    for (int i = 0; i < 16; i++) {
        float4 t = Wg[i];
        w[4*i+0] = t.x; w[4*i+1] = t.y; w[4*i+2] = t.z; w[4*i+3] = t.w;
    }
    __syncthreads();

    #pragma unroll 4
    for (int ii = 0; ii < 16; ii++) {
        int r = rq * 16 + ii;
        const float4* xr = (const float4*)(Xs + r * 64);
        float acc = 0.f;
        #pragma unroll
        for (int e4 = 0; e4 < 16; e4++) {
            float4 x = xr[e4];
            acc += x.x*w[4*e4+0] + x.y*w[4*e4+1] + x.z*w[4*e4+2] + x.w*w[4*e4+3];
        }
        int ri = rowBase + r;
        int h  = ri & (H_N - 1);
        int nl = ri >> 4;                 // = n*L + l   (H = 16)
        int n  = nl >> 11;                // / 2048
        int l  = nl & (L_S - 1);
        Y[(((size_t)(n*H_N + h)) * L_S + l) * D_H + d] = acc;
    }
}

// ============================================================================
// Kernel 2: flash attention.  Block = (n, h, 64-row q-tile), 256 threads.
// Per 64-wide k-tile: S = QK^T (4x4 micro-tiles) -> mask+scale -> online
// softmax (4 threads/row, shuffle reductions) -> O = O*corr + P V.
// ============================================================================
__global__ __launch_bounds__(256) void attn_kernel(const int* __restrict__ mask)
{
    extern __shared__ float sm[];
    float* Qts  = sm;                 // [e][r], stride QS (transposed)
    float* Kts  = Qts + 64*QS;        // [e][c], stride QS (transposed)
    float* Vs   = Kts + 64*QS;        // [c][d], stride QS
    float* Ss   = Vs  + 64*QS;        // [r][c], stride 64
    float* corr = Ss  + 64*64;        // [64]
    float* msh  = corr + 64;          // [64]
    float* lsh  = msh  + 64;          // [64]

    int qt = blockIdx.x, h = blockIdx.y, n = blockIdx.z;
    int tid = threadIdx.x;
    int tx = tid & 15, ty = tid >> 4;

    const float* Qg = g_q + ((size_t)(n*H_N + h) * L_S + qt*64) * D_H;
    const float* Kg = g_k +  (size_t)(n*H_N + h) * L_S * D_H;
    const float* Vg = g_v +  (size_t)(n*H_N + h) * L_S * D_H;
    const int*   mk = mask + n * L_S;

    // load Q tile transposed (once)
    for (int i = tid; i < 1024; i += 256) {
        int r = i >> 4, e4 = (i & 15) << 2;
        float4 v = ((const float4*)Qg)[i];
        Qts[(e4+0)*QS + r] = v.x;
        Qts[(e4+1)*QS + r] = v.y;
        Qts[(e4+2)*QS + r] = v.z;
        Qts[(e4+3)*QS + r] = v.w;
    }
    if (tid < 64) { msh[tid] = -3.0e38f; lsh[tid] = 0.f; }

    float O[4][4];
    #pragma unroll
    for (int i = 0; i < 4; i++)
        #pragma unroll
        for (int j = 0; j < 4; j++) O[i][j] = 0.f;

    for (int kt = 0; kt < L_S/64; kt++) {
        __syncthreads();   // previous tile fully consumed before overwrite

        const float4* K4 = (const float4*)(Kg + (size_t)kt * 64 * 64);
        const float4* V4 = (const float4*)(Vg + (size_t)kt * 64 * 64);
        for (int i = tid; i < 1024; i += 256) {
            int c = i >> 4, e4 = (i & 15) << 2;
            float4 kv = K4[i];
            Kts[(e4+0)*QS + c] = kv.x;
            Kts[(e4+1)*QS + c] = kv.y;
            Kts[(e4+2)*QS + c] = kv.z;
            Kts[(e4+3)*QS + c] = kv.w;
            float4 vv = V4[i];
            *(float4*)&Vs[c*QS + e4] = vv;
        }
        __syncthreads();

        // ---- S = Q K^T ----
        float acc[4][4];
        #pragma unroll
        for (int i = 0; i < 4; i++)
            #pragma unroll
            for (int j = 0; j < 4; j++) acc[i][j] = 0.f;

        #pragma unroll 16
        for (int e = 0; e < 64; e++) {
            float4 q4 = *(const float4*)&Qts[e*QS + ty*4];
            float4 k4 = *(const float4*)&Kts[e*QS + tx*4];
            float qv[4] = {q4.x, q4.y, q4.z, q4.w};
            float kv[4] = {k4.x, k4.y, k4.z, k4.w};
            #pragma unroll
            for (int i = 0; i < 4; i++)
                #pragma unroll
                for (int j = 0; j < 4; j++) acc[i][j] += qv[i]*kv[j];
        }

        // ---- mask + scale (1/sqrt(E) = 1/32), write Ss ----
        int kbase = kt * 64;
        #pragma unroll
        for (int j = 0; j < 4; j++) {
            int c = tx*4 + j;
            bool mz = (mk[kbase + c] == 0);
            #pragma unroll
            for (int i = 0; i < 4; i++) {
                float s = mz ? -1.0e30f : acc[i][j] * 0.03125f;
                Ss[(ty*4 + i)*64 + c] = s;
            }
        }
        __syncthreads();

        // ---- online softmax: 4 threads per row, shift-indexed for banks ----
        {
            int r  = tid >> 2;
            int qd = tid & 3;
            float* srow = Ss + r*64;

            float tmax = -3.0e38f;
            #pragma unroll
            for (int j = 0; j < 16; j++) {
                int c = (qd*16 + j + r) & 63;
                tmax = fmaxf(tmax, srow[c]);
            }
            tmax = fmaxf(tmax, __shfl_xor_sync(0xffffffffu, tmax, 1));
            tmax = fmaxf(tmax, __shfl_xor_sync(0xffffffffu, tmax, 2));

            float mold = msh[r];
            float mnew = fmaxf(mold, tmax);
            float cr   = exp2f((mold - mnew) * L2E);

            float psum = 0.f;
            #pragma unroll
            for (int j = 0; j < 16; j++) {
                int c = (qd*16 + j + r) & 63;
                float s = srow[c];
                float p = (s < -1.0e29f) ? 0.f : exp2f((s - mnew) * L2E);
                srow[c] = p;
                psum += p;
            }
            psum += __shfl_xor_sync(0xffffffffu, psum, 1);
            psum += __shfl_xor_sync(0xffffffffu, psum, 2);

            if (qd == 0) {
                msh[r]  = mnew;
                corr[r] = cr;
                lsh[r]  = lsh[r] * cr + psum;
            }
        }
        __syncthreads();

        // ---- O = O*corr + P @ V ----
        #pragma unroll
        for (int i = 0; i < 4; i++) {
            float cri = corr[ty*4 + i];
            #pragma unroll
            for (int j = 0; j < 4; j++) O[i][j] *= cri;
        }
        #pragma unroll 16
        for (int c = 0; c < 64; c++) {
            float pv[4];
            #pragma unroll
            for (int i = 0; i < 4; i++) pv[i] = Ss[(ty*4 + i)*64 + c];
            float4 v4 = *(const float4*)&Vs[c*QS + tx*4];
            float vv[4] = {v4.x, v4.y, v4.z, v4.w};
            #pragma unroll
            for (int i = 0; i < 4; i++)
                #pragma unroll
                for (int j = 0; j < 4; j++) O[i][j] += pv[i]*vv[j];
        }
    }

    // ---- epilogue: divide by l, write [n*L+l][E] for the output GEMM ----
    #pragma unroll
    for (int i = 0; i < 4; i++) {
        int r = ty*4 + i;
        float invl = 1.0f / lsh[r];
        float4 o;
        o.x = O[i][0]*invl; o.y = O[i][1]*invl;
        o.z = O[i][2]*invl; o.w = O[i][3]*invl;
        size_t row = (size_t)n*L_S + qt*64 + r;
        *(float4*)&g_ao[row*E_D + h*D_H + tx*4] = o;
    }
}

// ============================================================================
// Kernel 3: out = A @ Wo^T + bo.   A = g_ao [4096,1024], Wo [1024,1024].
// 64x64 block tile, BK=16, 4x4 register micro-tile, 256 threads.
// ============================================================================
__global__ __launch_bounds__(256) void out_gemm(
    const float* __restrict__ Wo, const float* __restrict__ bo,
    float* __restrict__ out)
{
    __shared__ float As[16][64];  // [k][m]
    __shared__ float Bs[16][64];  // [k][o]

    int nt = blockIdx.x * 64;
    int mt = blockIdx.y * 64;
    int tid = threadIdx.x;
    int tx = tid & 15, ty = tid >> 4;
    int lr = tid >> 2, k4 = (tid & 3) << 2;

    float acc[4][4];
    #pragma unroll
    for (int i = 0; i < 4; i++)
        #pragma unroll
        for (int j = 0; j < 4; j++) acc[i][j] = 0.f;

    for (int kt = 0; kt < E_D; kt += 16) {
        float4 a = *(const float4*)&g_ao[(size_t)(mt + lr)*E_D + kt + k4];
        float4 b = *(const float4*)&Wo  [(size_t)(nt + lr)*E_D + kt + k4];
        __syncthreads();   // previous compute done reading As/Bs
        As[k4+0][lr] = a.x; As[k4+1][lr] = a.y; As[k4+2][lr] = a.z; As[k4+3][lr] = a.w;
        Bs[k4+0][lr] = b.x; Bs[k4+1][lr] = b.y; Bs[k4+2][lr] = b.z; Bs[k4+3][lr] = b.w;
        __syncthreads();

        #pragma unroll
        for (int k = 0; k < 16; k++) {
            float4 a4 = *(const float4*)&As[k][ty*4];
            float4 b4 = *(const float4*)&Bs[k][tx*4];
            float av[4] = {a4.x, a4.y, a4.z, a4.w};
            float bv[4] = {b4.x, b4.y, b4.z, b4.w};
            #pragma unroll
            for (int i = 0; i < 4; i++)
                #pragma unroll
                for (int j = 0; j < 4; j++) acc[i][j] += av[i]*bv[j];
        }
    }

    int c0 = nt + tx*4;
    float4 bb = *(const float4*)&bo[c0];
    float bias[4] = {bb.x, bb.y, bb.z, bb.w};
    #pragma unroll
    for (int i = 0; i < 4; i++) {
        int r = mt + ty*4 + i;
        float4 o;
        o.x = acc[i][0] + bias[0];
        o.y = acc[i][1] + bias[1];
        o.z = acc[i][2] + bias[2];
        o.w = acc[i][3] + bias[3];
        *(float4*)&out[(size_t)r*E_D + c0] = o;
    }
}

// ============================================================================
extern "C" void kernel_launch(void* const* d_in, const int* in_sizes, int n_in,
                              void* d_out, int out_size)
{
    const float* values = (const float*)d_in[0];
    const float* keysp  = (const float*)d_in[1];
    const float* query  = (const float*)d_in[2];
    const int*   mask   = (const int*)  d_in[3];
    const float* Wv     = (const float*)d_in[4];
    const float* Wk     = (const float*)d_in[5];
    const float* Wq     = (const float*)d_in[6];
    const float* Wo     = (const float*)d_in[7];
    const float* bo     = (const float*)d_in[8];
    float* out = (float*)d_out;

    // 1. QKV projections (3 * 65536 rows of 64x64 GEMV)
    proj_kernel<<<dim3((N_B*L_S*H_N)/64, 3), 256>>>(values, keysp, query, Wv, Wk, Wq);

    // 2. flash attention (needs 69 KB dynamic smem; attribute set is not a
    //    stream op, safe under graph capture, idempotent per call)
    int smem = (64*QS*3 + 64*64 + 3*64) * (int)sizeof(float);
    cudaFuncSetAttribute(attn_kernel,
                         cudaFuncAttributeMaxDynamicSharedMemorySize, smem);
    attn_kernel<<<dim3(L_S/64, H_N, N_B), 256, smem>>>(mask);

    // 3. output projection + bias
    out_gemm<<<dim3(E_D/64, (N_B*L_S)/64), 256>>>(Wo, bo, out);
}

// round 2
// speedup vs baseline: 2.6719x; 2.6719x over previous
#include <cuda_runtime.h>
#include <cstdint>
#include <cstddef>

#define N_B 2
#define L_S 2048
#define E_D 1024
#define H_N 16
#define D_H 64
#define L2E 1.44269504088896341f

// -------- scratch (device globals; no allocations allowed) --------
__device__ float g_q [N_B*H_N*L_S*D_H];   // [n][h][l][d]
__device__ float g_k [N_B*H_N*L_S*D_H];
__device__ float g_v [N_B*H_N*L_S*D_H];
__device__ float g_ao[N_B*L_S*E_D];       // attention output [n*L+l][E]

// ---------------- TF32 mma helpers (m16n8k8, row.col) ----------------
__device__ __forceinline__ uint32_t f2tf(float f) {
    uint32_t u; asm("cvt.rna.tf32.f32 %0, %1;" : "=r"(u) : "f"(f)); return u;
}
__device__ __forceinline__ void mma8(float* d, const uint32_t* a, const uint32_t* b) {
    asm("mma.sync.aligned.m16n8k8.row.col.f32.tf32.tf32.f32 "
        "{%0,%1,%2,%3},{%4,%5,%6,%7},{%8,%9},{%0,%1,%2,%3};"
        : "+f"(d[0]), "+f"(d[1]), "+f"(d[2]), "+f"(d[3])
        : "r"(a[0]), "r"(a[1]), "r"(a[2]), "r"(a[3]),
          "r"(b[0]), "r"(b[1]));
}
// Fragment maps (m16n8k8 tf32):
//  A: a0=(g,q) a1=(g+8,q) a2=(g,q+4) a3=(g+8,q+4)   [g=lane>>2, q=lane&3; k-cols]
//  B: b0=(k=q, n=g) b1=(k=q+4, n=g)
//  C: c0=(g,2q) c1=(g,2q+1) c2=(g+8,2q) c3=(g+8,2q+1)

// ============================================================================
// Kernel 1: QKV projection via mma.  Y[ri,d] = sum_e X[ri,e]*W[d,e]
// Block: 64 rows, 128 threads (4 warps, m16 strip each), N=64, K=64.
// ============================================================================
__global__ __launch_bounds__(128) void proj_mma(
    const float* __restrict__ vals, const float* __restrict__ keys,
    const float* __restrict__ qry,
    const float* __restrict__ Wv, const float* __restrict__ Wk,
    const float* __restrict__ Wq)
{
    const float* X; const float* W; float* Y;
    int which = blockIdx.y;
    if (which == 0)      { X = vals; W = Wv; Y = g_v; }
    else if (which == 1) { X = keys; W = Wk; Y = g_k; }
    else                 { X = qry;  W = Wq; Y = g_q; }

    __shared__ float Xs[64*68];
    __shared__ float Ws[64*68];

    int rowBase = blockIdx.x * 64;
    int tid = threadIdx.x, warp = tid >> 5, lane = tid & 31;
    int g = lane >> 2, q = lane & 3;

    const float4* Xg = (const float4*)(X + (size_t)rowBase * 64);
    const float4* Wg = (const float4*)W;
    for (int i = tid; i < 1024; i += 128) {
        int r = i >> 4, c4 = (i & 15) << 2;
        *(float4*)&Xs[r*68 + c4] = Xg[i];
        *(float4*)&Ws[r*68 + c4] = Wg[i];
    }
    __syncthreads();

    int m0 = warp * 16;
    uint32_t a[8][4];
    #pragma unroll
    for (int kk = 0; kk < 8; kk++) {
        a[kk][0] = f2tf(Xs[(m0+g  )*68 + kk*8 + q    ]);
        a[kk][1] = f2tf(Xs[(m0+g+8)*68 + kk*8 + q    ]);
        a[kk][2] = f2tf(Xs[(m0+g  )*68 + kk*8 + q + 4]);
        a[kk][3] = f2tf(Xs[(m0+g+8)*68 + kk*8 + q + 4]);
    }

    float acc[8][4];
    #pragma unroll
    for (int nf = 0; nf < 8; nf++)
        #pragma unroll
        for (int t = 0; t < 4; t++) acc[nf][t] = 0.f;

    #pragma unroll
    for (int kk = 0; kk < 8; kk++) {
        #pragma unroll
        for (int nf = 0; nf < 8; nf++) {
            uint32_t b[2];
            b[0] = f2tf(Ws[(nf*8+g)*68 + kk*8 + q    ]);
            b[1] = f2tf(Ws[(nf*8+g)*68 + kk*8 + q + 4]);
            mma8(acc[nf], a[kk], b);
        }
    }

    // scatter-store: row ri -> (n,h,l)
    int r0 = rowBase + m0 + g;
    int r1 = r0 + 8;
    int h0 = r0 & 15, nl0 = r0 >> 4;
    int h1 = r1 & 15, nl1 = r1 >> 4;
    size_t base0 = (((size_t)((nl0 >> 11)*H_N + h0))*L_S + (nl0 & (L_S-1)))*D_H;
    size_t base1 = (((size_t)((nl1 >> 11)*H_N + h1))*L_S + (nl1 & (L_S-1)))*D_H;
    #pragma unroll
    for (int nf = 0; nf < 8; nf++) {
        int c = nf*8 + 2*q;
        *(float2*)&Y[base0 + c] = make_float2(acc[nf][0], acc[nf][1]);
        *(float2*)&Y[base1 + c] = make_float2(acc[nf][2], acc[nf][3]);
    }
}

// ============================================================================
// Kernel 2: flash attention with TF32 mma.
// Block = (qtile64, h, n), 128 threads (4 warps, m16 strip each).
// ============================================================================
__global__ __launch_bounds__(128) void attn_mma(const int* __restrict__ mask)
{
    extern __shared__ float sm[];
    float* Ks   = sm;                // [c][e] stride 68
    float* Vs   = Ks + 64*68;        // [c][d] stride 68
    float* Ss   = Vs + 64*68;        // [r][c] stride 68  (also Q staging)
    float* corr = Ss + 64*68;        // [64]
    float* msh  = corr + 64;
    float* lsh  = msh  + 64;
    int*   msks = (int*)(lsh + 64);  // [64]

    int qt = blockIdx.x, h = blockIdx.y, n = blockIdx.z;
    int tid = threadIdx.x, warp = tid >> 5, lane = tid & 31;
    int g = lane >> 2, q = lane & 3;
    int m0 = warp * 16;

    const float* Qg = g_q + ((size_t)(n*H_N + h) * L_S + qt*64) * D_H;
    const float* Kg = g_k +  (size_t)(n*H_N + h) * L_S * D_H;
    const float* Vg = g_v +  (size_t)(n*H_N + h) * L_S * D_H;
    const int*   mk = mask + n * L_S;

    // stage Q in Ss, grab persistent A-fragments
    for (int i = tid; i < 1024; i += 128) {
        int r = i >> 4, c4 = (i & 15) << 2;
        *(float4*)&Ss[r*68 + c4] = ((const float4*)Qg)[i];
    }
    if (tid < 64) { msh[tid] = -3.0e38f; lsh[tid] = 0.f; }
    __syncthreads();

    uint32_t qa[8][4];
    #pragma unroll
    for (int kk = 0; kk < 8; kk++) {
        qa[kk][0] = f2tf(Ss[(m0+g  )*68 + kk*8 + q    ]);
        qa[kk][1] = f2tf(Ss[(m0+g+8)*68 + kk*8 + q    ]);
        qa[kk][2] = f2tf(Ss[(m0+g  )*68 + kk*8 + q + 4]);
        qa[kk][3] = f2tf(Ss[(m0+g+8)*68 + kk*8 + q + 4]);
    }

    float O[8][4];
    #pragma unroll
    for (int nf = 0; nf < 8; nf++)
        #pragma unroll
        for (int t = 0; t < 4; t++) O[nf][t] = 0.f;

    for (int kt = 0; kt < L_S/64; kt++) {
        __syncthreads();   // previous tile fully consumed

        const float4* K4 = (const float4*)(Kg + (size_t)kt * 64 * 64);
        const float4* V4 = (const float4*)(Vg + (size_t)kt * 64 * 64);
        for (int i = tid; i < 2048; i += 128) {
            int i2 = i & 1023;
            int r = i2 >> 4, c4 = (i2 & 15) << 2;
            if (i < 1024) *(float4*)&Ks[r*68 + c4] = K4[i2];
            else          *(float4*)&Vs[r*68 + c4] = V4[i2];
        }
        if (tid < 64) msks[tid] = mk[kt*64 + tid];
        __syncthreads();

        // ---- S = Q K^T ----
        float sacc[8][4];
        #pragma unroll
        for (int nf = 0; nf < 8; nf++)
            #pragma unroll
            for (int t = 0; t < 4; t++) sacc[nf][t] = 0.f;

        #pragma unroll
        for (int kk = 0; kk < 8; kk++) {
            #pragma unroll
            for (int nf = 0; nf < 8; nf++) {
                uint32_t b[2];
                b[0] = f2tf(Ks[(nf*8+g)*68 + kk*8 + q    ]);
                b[1] = f2tf(Ks[(nf*8+g)*68 + kk*8 + q + 4]);
                mma8(sacc[nf], qa[kk], b);
            }
        }

        // ---- mask + scale (1/sqrt(1024) = 1/32), store to Ss ----
        #pragma unroll
        for (int nf = 0; nf < 8; nf++) {
            int c = nf*8 + 2*q;
            bool m0ok = (msks[c]   != 0);
            bool m1ok = (msks[c+1] != 0);
            float s0 = m0ok ? sacc[nf][0]*0.03125f : -1.0e30f;
            float s1 = m1ok ? sacc[nf][1]*0.03125f : -1.0e30f;
            float s2 = m0ok ? sacc[nf][2]*0.03125f : -1.0e30f;
            float s3 = m1ok ? sacc[nf][3]*0.03125f : -1.0e30f;
            *(float2*)&Ss[(m0+g  )*68 + c] = make_float2(s0, s1);
            *(float2*)&Ss[(m0+g+8)*68 + c] = make_float2(s2, s3);
        }
        __syncthreads();

        // ---- online softmax: 2 threads per row ----
        {
            int r = tid >> 1, half = tid & 1;
            float* srow = Ss + r*68 + half*32;

            float tmax = -3.0e38f;
            #pragma unroll
            for (int j4 = 0; j4 < 8; j4++) {
                float4 v = *(float4*)&srow[j4*4];
                tmax = fmaxf(tmax, fmaxf(fmaxf(v.x, v.y), fmaxf(v.z, v.w)));
            }
            tmax = fmaxf(tmax, __shfl_xor_sync(0xffffffffu, tmax, 1));

            float mold = msh[r];
            float mnew = fmaxf(mold, tmax);
            float cr   = exp2f((mold - mnew) * L2E);

            float psum = 0.f;
            #pragma unroll
            for (int j4 = 0; j4 < 8; j4++) {
                float4 v = *(float4*)&srow[j4*4];
                float4 p;
                p.x = (v.x < -1.0e29f) ? 0.f : exp2f((v.x - mnew) * L2E);
                p.y = (v.y < -1.0e29f) ? 0.f : exp2f((v.y - mnew) * L2E);
                p.z = (v.z < -1.0e29f) ? 0.f : exp2f((v.z - mnew) * L2E);
                p.w = (v.w < -1.0e29f) ? 0.f : exp2f((v.w - mnew) * L2E);
                *(float4*)&srow[j4*4] = p;
                psum += p.x + p.y + p.z + p.w;
            }
            psum += __shfl_xor_sync(0xffffffffu, psum, 1);

            if (half == 0) {
                msh[r]  = mnew;
                corr[r] = cr;
                lsh[r]  = lsh[r] * cr + psum;
            }
        }
        __syncthreads();

        // ---- O = O*corr + P @ V ----
        float cr0 = corr[m0+g], cr1 = corr[m0+g+8];
        #pragma unroll
        for (int nf = 0; nf < 8; nf++) {
            O[nf][0] *= cr0; O[nf][1] *= cr0;
            O[nf][2] *= cr1; O[nf][3] *= cr1;
        }
        #pragma unroll
        for (int ck = 0; ck < 8; ck++) {
            uint32_t pa[4];
            pa[0] = f2tf(Ss[(m0+g  )*68 + ck*8 + q    ]);
            pa[1] = f2tf(Ss[(m0+g+8)*68 + ck*8 + q    ]);
            pa[2] = f2tf(Ss[(m0+g  )*68 + ck*8 + q + 4]);
            pa[3] = f2tf(Ss[(m0+g+8)*68 + ck*8 + q + 4]);
            #pragma unroll
            for (int nf = 0; nf < 8; nf++) {
                uint32_t b[2];
                b[0] = f2tf(Vs[(ck*8 + q    )*68 + nf*8 + g]);
                b[1] = f2tf(Vs[(ck*8 + q + 4)*68 + nf*8 + g]);
                mma8(O[nf], pa, b);
            }
        }
    }

    // ---- epilogue: divide by row sum, write [n*L+l][E] ----
    float invl0 = 1.0f / lsh[m0+g];
    float invl1 = 1.0f / lsh[m0+g+8];
    size_t row0 = ((size_t)n*L_S + qt*64 + m0 + g    ) * E_D + h*D_H;
    size_t row1 = ((size_t)n*L_S + qt*64 + m0 + g + 8) * E_D + h*D_H;
    #pragma unroll
    for (int nf = 0; nf < 8; nf++) {
        int c = nf*8 + 2*q;
        *(float2*)&g_ao[row0 + c] = make_float2(O[nf][0]*invl0, O[nf][1]*invl0);
        *(float2*)&g_ao[row1 + c] = make_float2(O[nf][2]*invl1, O[nf][3]*invl1);
    }
}

// ============================================================================
// Kernel 3: out = A @ Wo^T + bo.  A=[4096,1024], Wo=[1024,1024] row-major.
// 64x64 block tile, BK=32, 128 threads (4 warps, m16 strips).
// ============================================================================
__global__ __launch_bounds__(128) void out_gemm_mma(
    const float* __restrict__ Wo, const float* __restrict__ bo,
    float* __restrict__ out)
{
    __shared__ float As[64*36];
    __shared__ float Bs[64*36];

    int nt = blockIdx.x * 64;
    int mt = blockIdx.y * 64;
    int tid = threadIdx.x, warp = tid >> 5, lane = tid & 31;
    int g = lane >> 2, q = lane & 3;
    int m0 = warp * 16;

    float acc[8][4];
    #pragma unroll
    for (int nf = 0; nf < 8; nf++)
        #pragma unroll
        for (int t = 0; t < 4; t++) acc[nf][t] = 0.f;

    for (int kt = 0; kt < E_D; kt += 32) {
        __syncthreads();
        for (int i = tid; i < 512; i += 128) {
            int r = i >> 3, c4 = (i & 7) << 2;
            *(float4*)&As[r*36 + c4] = *(const float4*)&g_ao[(size_t)(mt + r)*E_D + kt + c4];
            *(float4*)&Bs[r*36 + c4] = *(const float4*)&Wo  [(size_t)(nt + r)*E_D + kt + c4];
        }
        __syncthreads();

        #pragma unroll
        for (int kk = 0; kk < 4; kk++) {
            uint32_t a[4];
            a[0] = f2tf(As[(m0+g  )*36 + kk*8 + q    ]);
            a[1] = f2tf(As[(m0+g+8)*36 + kk*8 + q    ]);
            a[2] = f2tf(As[(m0+g  )*36 + kk*8 + q + 4]);
            a[3] = f2tf(As[(m0+g+8)*36 + kk*8 + q + 4]);
            #pragma unroll
            for (int nf = 0; nf < 8; nf++) {
                uint32_t b[2];
                b[0] = f2tf(Bs[(nf*8+g)*36 + kk*8 + q    ]);
                b[1] = f2tf(Bs[(nf*8+g)*36 + kk*8 + q + 4]);
                mma8(acc[nf], a, b);
            }
        }
    }

    size_t row0 = (size_t)(mt + m0 + g    ) * E_D + nt;
    size_t row1 = (size_t)(mt + m0 + g + 8) * E_D + nt;
    #pragma unroll
    for (int nf = 0; nf < 8; nf++) {
        int c = nf*8 + 2*q;
        float2 bb = *(const float2*)&bo[nt + c];
        *(float2*)&out[row0 + c] = make_float2(acc[nf][0] + bb.x, acc[nf][1] + bb.y);
        *(float2*)&out[row1 + c] = make_float2(acc[nf][2] + bb.x, acc[nf][3] + bb.y);
    }
}

// ============================================================================
extern "C" void kernel_launch(void* const* d_in, const int* in_sizes, int n_in,
                              void* d_out, int out_size)
{
    const float* values = (const float*)d_in[0];
    const float* keysp  = (const float*)d_in[1];
    const float* query  = (const float*)d_in[2];
    const int*   mask   = (const int*)  d_in[3];
    const float* Wv     = (const float*)d_in[4];
    const float* Wk     = (const float*)d_in[5];
    const float* Wq     = (const float*)d_in[6];
    const float* Wo     = (const float*)d_in[7];
    const float* bo     = (const float*)d_in[8];
    float* out = (float*)d_out;

    // 1. QKV projections
    proj_mma<<<dim3((N_B*L_S*H_N)/64, 3), 128>>>(values, keysp, query, Wv, Wk, Wq);

    // 2. flash attention (dynamic smem 52 KB; attribute set is capture-safe)
    int smem = (3*64*68 + 3*64 + 64) * (int)sizeof(float);
    cudaFuncSetAttribute(attn_mma,
                         cudaFuncAttributeMaxDynamicSharedMemorySize, smem);
    attn_mma<<<dim3(L_S/64, H_N, N_B), 128, smem>>>(mask);

    // 3. output projection + bias
    out_gemm_mma<<<dim3(E_D/64, (N_B*L_S)/64), 128>>>(Wo, bo, out);
}

// round 3
// speedup vs baseline: 3.0104x; 1.1267x over previous
#include <cuda_runtime.h>
#include <cstdint>
#include <cstddef>

#define N_B 2
#define L_S 2048
#define E_D 1024
#define H_N 16
#define D_H 64
#define L2E 1.44269504088896341f

// -------- scratch (device globals; no allocations allowed) --------
// All of these hold TF32-pre-rounded values (bit pattern of cvt.rna.tf32).
__device__ float g_q [N_B*H_N*L_S*D_H];   // [n][h][l][d]
__device__ float g_k [N_B*H_N*L_S*D_H];
__device__ float g_v [N_B*H_N*L_S*D_H];
__device__ float g_ao[N_B*L_S*E_D];       // attention output [n*L+l][E]
__device__ float g_wo[E_D*E_D];           // Wo, TF32-rounded

// ---------------- TF32 mma helpers (m16n8k8, row.col) ----------------
__device__ __forceinline__ uint32_t f2tf(float f) {
    uint32_t u; asm("cvt.rna.tf32.f32 %0, %1;" : "=r"(u) : "f"(f)); return u;
}
__device__ __forceinline__ float f2tf_f(float f) {
    return __uint_as_float(f2tf(f));
}
__device__ __forceinline__ void mma8(float* d, const uint32_t* a, const uint32_t* b) {
    asm("mma.sync.aligned.m16n8k8.row.col.f32.tf32.tf32.f32 "
        "{%0,%1,%2,%3},{%4,%5,%6,%7},{%8,%9},{%0,%1,%2,%3};"
        : "+f"(d[0]), "+f"(d[1]), "+f"(d[2]), "+f"(d[3])
        : "r"(a[0]), "r"(a[1]), "r"(a[2]), "r"(a[3]),
          "r"(b[0]), "r"(b[1]));
}
// Fragment maps (m16n8k8 tf32), g=lane>>2, q=lane&3:
//  A: a0=(g,q) a1=(g+8,q) a2=(g,q+4) a3=(g+8,q+4)
//  B: b0=(k=q, n=g) b1=(k=q+4, n=g)
//  C: c0=(g,2q) c1=(g,2q+1) c2=(g+8,2q) c3=(g+8,2q+1)

// ============================================================================
// Kernel 0: one-time TF32 rounding of Wo (runs once per launch, ~2us)
// ============================================================================
__global__ __launch_bounds__(256) void cvt_wo_kernel(const float* __restrict__ Wo)
{
    int i = blockIdx.x * 256 + threadIdx.x;
    float4 v = ((const float4*)Wo)[i];
    v.x = f2tf_f(v.x); v.y = f2tf_f(v.y); v.z = f2tf_f(v.z); v.w = f2tf_f(v.w);
    ((float4*)g_wo)[i] = v;
}

// ============================================================================
// Kernel 1: QKV projection via mma; outputs stored TF32-pre-rounded.
// Block: 64 rows, 128 threads (4 warps, m16 strip each), N=64, K=64.
// ============================================================================
__global__ __launch_bounds__(128) void proj_mma(
    const float* __restrict__ vals, const float* __restrict__ keys,
    const float* __restrict__ qry,
    const float* __restrict__ Wv, const float* __restrict__ Wk,
    const float* __restrict__ Wq)
{
    const float* X; const float* W; float* Y;
    int which = blockIdx.y;
    if (which == 0)      { X = vals; W = Wv; Y = g_v; }
    else if (which == 1) { X = keys; W = Wk; Y = g_k; }
    else                 { X = qry;  W = Wq; Y = g_q; }

    __shared__ float Xs[64*68];
    __shared__ float Ws[64*68];

    int rowBase = blockIdx.x * 64;
    int tid = threadIdx.x, warp = tid >> 5, lane = tid & 31;
    int g = lane >> 2, q = lane & 3;

    const float4* Xg = (const float4*)(X + (size_t)rowBase * 64);
    const float4* Wg = (const float4*)W;
    for (int i = tid; i < 1024; i += 128) {
        int r = i >> 4, c4 = (i & 15) << 2;
        *(float4*)&Xs[r*68 + c4] = Xg[i];
        *(float4*)&Ws[r*68 + c4] = Wg[i];
    }
    __syncthreads();

    int m0 = warp * 16;
    uint32_t a[8][4];
    #pragma unroll
    for (int kk = 0; kk < 8; kk++) {
        a[kk][0] = f2tf(Xs[(m0+g  )*68 + kk*8 + q    ]);
        a[kk][1] = f2tf(Xs[(m0+g+8)*68 + kk*8 + q    ]);
        a[kk][2] = f2tf(Xs[(m0+g  )*68 + kk*8 + q + 4]);
        a[kk][3] = f2tf(Xs[(m0+g+8)*68 + kk*8 + q + 4]);
    }

    float acc[8][4];
    #pragma unroll
    for (int nf = 0; nf < 8; nf++)
        #pragma unroll
        for (int t = 0; t < 4; t++) acc[nf][t] = 0.f;

    #pragma unroll
    for (int kk = 0; kk < 8; kk++) {
        #pragma unroll
        for (int nf = 0; nf < 8; nf++) {
            uint32_t b[2];
            b[0] = f2tf(Ws[(nf*8+g)*68 + kk*8 + q    ]);
            b[1] = f2tf(Ws[(nf*8+g)*68 + kk*8 + q + 4]);
            mma8(acc[nf], a[kk], b);
        }
    }

    // scatter-store pre-rounded: row ri -> (n,h,l)
    int r0 = rowBase + m0 + g;
    int r1 = r0 + 8;
    int h0 = r0 & 15, nl0 = r0 >> 4;
    int h1 = r1 & 15, nl1 = r1 >> 4;
    size_t base0 = (((size_t)((nl0 >> 11)*H_N + h0))*L_S + (nl0 & (L_S-1)))*D_H;
    size_t base1 = (((size_t)((nl1 >> 11)*H_N + h1))*L_S + (nl1 & (L_S-1)))*D_H;
    #pragma unroll
    for (int nf = 0; nf < 8; nf++) {
        int c = nf*8 + 2*q;
        *(float2*)&Y[base0 + c] = make_float2(f2tf_f(acc[nf][0]), f2tf_f(acc[nf][1]));
        *(float2*)&Y[base1 + c] = make_float2(f2tf_f(acc[nf][2]), f2tf_f(acc[nf][3]));
    }
}

// ============================================================================
// Kernel 2: flash attention, TF32 mma, q-tile 128, 256 threads (8 warps).
// Q/K/V are pre-rounded -> fragments are plain bit-loads (no cvt).
// ============================================================================
#define KS_STRIDE 68
#define VS_STRIDE 72
#define SS_STRIDE 68

__global__ __launch_bounds__(256) void attn_mma(const int* __restrict__ mask)
{
    extern __shared__ float sm[];
    float* Ks   = sm;                       // [64][68]
    float* Vs   = Ks + 64*KS_STRIDE;        // [64][72]
    float* Ss   = Vs + 64*VS_STRIDE;        // [128][68] (also Q staging)
    float* corr = Ss + 128*SS_STRIDE;       // [128]
    float* msh  = corr + 128;
    float* lsh  = msh  + 128;
    int*   msks = (int*)(lsh + 128);        // [64]

    int qt = blockIdx.x, h = blockIdx.y, n = blockIdx.z;
    int tid = threadIdx.x, warp = tid >> 5, lane = tid & 31;
    int g = lane >> 2, q = lane & 3;
    int m0 = warp * 16;

    const float* Qg = g_q + ((size_t)(n*H_N + h) * L_S + qt*128) * D_H;
    const float* Kg = g_k +  (size_t)(n*H_N + h) * L_S * D_H;
    const float* Vg = g_v +  (size_t)(n*H_N + h) * L_S * D_H;
    const int*   mk = mask + n * L_S;

    // stage Q tile (128x64) in Ss, grab persistent A-fragments
    for (int i = tid; i < 2048; i += 256) {
        int r = i >> 4, c4 = (i & 15) << 2;
        *(float4*)&Ss[r*SS_STRIDE + c4] = ((const float4*)Qg)[i];
    }
    if (tid < 128) { msh[tid] = -3.0e38f; lsh[tid] = 0.f; }
    __syncthreads();

    uint32_t qa[8][4];
    #pragma unroll
    for (int kk = 0; kk < 8; kk++) {
        qa[kk][0] = __float_as_uint(Ss[(m0+g  )*SS_STRIDE + kk*8 + q    ]);
        qa[kk][1] = __float_as_uint(Ss[(m0+g+8)*SS_STRIDE + kk*8 + q    ]);
        qa[kk][2] = __float_as_uint(Ss[(m0+g  )*SS_STRIDE + kk*8 + q + 4]);
        qa[kk][3] = __float_as_uint(Ss[(m0+g+8)*SS_STRIDE + kk*8 + q + 4]);
    }

    float O[8][4];
    #pragma unroll
    for (int nf = 0; nf < 8; nf++)
        #pragma unroll
        for (int t = 0; t < 4; t++) O[nf][t] = 0.f;

    for (int kt = 0; kt < L_S/64; kt++) {
        __syncthreads();   // previous tile fully consumed

        const float4* K4 = (const float4*)(Kg + (size_t)kt * 64 * 64);
        const float4* V4 = (const float4*)(Vg + (size_t)kt * 64 * 64);
        for (int i = tid; i < 2048; i += 256) {
            int i2 = i & 1023;
            int r = i2 >> 4, c4 = (i2 & 15) << 2;
            if (i < 1024) *(float4*)&Ks[r*KS_STRIDE + c4] = K4[i2];
            else          *(float4*)&Vs[r*VS_STRIDE + c4] = V4[i2];
        }
        if (tid < 64) msks[tid] = mk[kt*64 + tid];
        __syncthreads();

        // ---- S = Q K^T (no cvt: K pre-rounded) ----
        float sacc[8][4];
        #pragma unroll
        for (int nf = 0; nf < 8; nf++)
            #pragma unroll
            for (int t = 0; t < 4; t++) sacc[nf][t] = 0.f;

        #pragma unroll
        for (int kk = 0; kk < 8; kk++) {
            #pragma unroll
            for (int nf = 0; nf < 8; nf++) {
                uint32_t b[2];
                b[0] = __float_as_uint(Ks[(nf*8+g)*KS_STRIDE + kk*8 + q    ]);
                b[1] = __float_as_uint(Ks[(nf*8+g)*KS_STRIDE + kk*8 + q + 4]);
                mma8(sacc[nf], qa[kk], b);
            }
        }

        // ---- mask + scale (1/sqrt(1024) = 1/32), store to Ss ----
        #pragma unroll
        for (int nf = 0; nf < 8; nf++) {
            int c = nf*8 + 2*q;
            bool m0ok = (msks[c]   != 0);
            bool m1ok = (msks[c+1] != 0);
            float s0 = m0ok ? sacc[nf][0]*0.03125f : -1.0e30f;
            float s1 = m1ok ? sacc[nf][1]*0.03125f : -1.0e30f;
            float s2 = m0ok ? sacc[nf][2]*0.03125f : -1.0e30f;
            float s3 = m1ok ? sacc[nf][3]*0.03125f : -1.0e30f;
            *(float2*)&Ss[(m0+g  )*SS_STRIDE + c] = make_float2(s0, s1);
            *(float2*)&Ss[(m0+g+8)*SS_STRIDE + c] = make_float2(s2, s3);
        }
        __syncthreads();

        // ---- online softmax: 2 threads per row (256 thr / 128 rows) ----
        {
            int r = tid >> 1, half = tid & 1;
            float* srow = Ss + r*SS_STRIDE + half*32;

            float tmax = -3.0e38f;
            #pragma unroll
            for (int j4 = 0; j4 < 8; j4++) {
                float4 v = *(float4*)&srow[j4*4];
                tmax = fmaxf(tmax, fmaxf(fmaxf(v.x, v.y), fmaxf(v.z, v.w)));
            }
            tmax = fmaxf(tmax, __shfl_xor_sync(0xffffffffu, tmax, 1));

            float mold = msh[r];
            float mnew = fmaxf(mold, tmax);
            float cr   = exp2f((mold - mnew) * L2E);

            // masked entries (-1e30) underflow to exact 0; a fully-masked
            // prefix yields p=1 entries that are later annihilated by cr=0.
            float psum = 0.f;
            #pragma unroll
            for (int j4 = 0; j4 < 8; j4++) {
                float4 v = *(float4*)&srow[j4*4];
                float4 p;
                p.x = exp2f((v.x - mnew) * L2E);
                p.y = exp2f((v.y - mnew) * L2E);
                p.z = exp2f((v.z - mnew) * L2E);
                p.w = exp2f((v.w - mnew) * L2E);
                *(float4*)&srow[j4*4] = p;
                psum += p.x + p.y + p.z + p.w;
            }
            psum += __shfl_xor_sync(0xffffffffu, psum, 1);

            if (half == 0) {
                msh[r]  = mnew;
                corr[r] = cr;
                lsh[r]  = lsh[r] * cr + psum;
            }
        }
        __syncthreads();

        // ---- O = O*corr + P @ V (V pre-rounded: no cvt; P needs cvt) ----
        float cr0 = corr[m0+g], cr1 = corr[m0+g+8];
        #pragma unroll
        for (int nf = 0; nf < 8; nf++) {
            O[nf][0] *= cr0; O[nf][1] *= cr0;
            O[nf][2] *= cr1; O[nf][3] *= cr1;
        }
        #pragma unroll
        for (int ck = 0; ck < 8; ck++) {
            uint32_t pa[4];
            pa[0] = f2tf(Ss[(m0+g  )*SS_STRIDE + ck*8 + q    ]);
            pa[1] = f2tf(Ss[(m0+g+8)*SS_STRIDE + ck*8 + q    ]);
            pa[2] = f2tf(Ss[(m0+g  )*SS_STRIDE + ck*8 + q + 4]);
            pa[3] = f2tf(Ss[(m0+g+8)*SS_STRIDE + ck*8 + q + 4]);
            #pragma unroll
            for (int nf = 0; nf < 8; nf++) {
                uint32_t b[2];
                b[0] = __float_as_uint(Vs[(ck*8 + q    )*VS_STRIDE + nf*8 + g]);
                b[1] = __float_as_uint(Vs[(ck*8 + q + 4)*VS_STRIDE + nf*8 + g]);
                mma8(O[nf], pa, b);
            }
        }
    }

    // ---- epilogue: divide by row sum, store TF32-pre-rounded ----
    float invl0 = 1.0f / lsh[m0+g];
    float invl1 = 1.0f / lsh[m0+g+8];
    size_t row0 = ((size_t)n*L_S + qt*128 + m0 + g    ) * E_D + h*D_H;
    size_t row1 = ((size_t)n*L_S + qt*128 + m0 + g + 8) * E_D + h*D_H;
    #pragma unroll
    for (int nf = 0; nf < 8; nf++) {
        int c = nf*8 + 2*q;
        *(float2*)&g_ao[row0 + c] =
            make_float2(f2tf_f(O[nf][0]*invl0), f2tf_f(O[nf][1]*invl0));
        *(float2*)&g_ao[row1 + c] =
            make_float2(f2tf_f(O[nf][2]*invl1), f2tf_f(O[nf][3]*invl1));
    }
}

// ============================================================================
// Kernel 3: out = A @ Wo^T + bo.  A=g_ao [4096,1024], B=g_wo [1024,1024],
// both pre-rounded (zero cvt). 128x128 tile, BK=32, 256 threads (8 warps:
// 4 m-warps x 2 n-warps; warp tile m32 x n64).
// ============================================================================
__global__ __launch_bounds__(256) void out_gemm_mma(
    const float* __restrict__ bo, float* __restrict__ out)
{
    __shared__ float As[128*36];
    __shared__ float Bs[128*36];

    int nt = blockIdx.x * 128;
    int mt = blockIdx.y * 128;
    int tid = threadIdx.x, warp = tid >> 5, lane = tid & 31;
    int g = lane >> 2, q = lane & 3;
    int wm = warp & 3, wn = warp >> 2;

    float acc[2][8][4];
    #pragma unroll
    for (int mi = 0; mi < 2; mi++)
        #pragma unroll
        for (int nf = 0; nf < 8; nf++)
            #pragma unroll
            for (int t = 0; t < 4; t++) acc[mi][nf][t] = 0.f;

    for (int kt = 0; kt < E_D; kt += 32) {
        __syncthreads();
        for (int i = tid; i < 2048; i += 256) {
            int i2 = i & 1023;
            int r = i2 >> 3, c4 = (i2 & 7) << 2;
            if (i < 1024)
                *(float4*)&As[r*36 + c4] = *(const float4*)&g_ao[(size_t)(mt + r)*E_D + kt + c4];
            else
                *(float4*)&Bs[r*36 + c4] = *(const float4*)&g_wo[(size_t)(nt + r)*E_D + kt + c4];
        }
        __syncthreads();

        #pragma unroll
        for (int kk = 0; kk < 4; kk++) {
            uint32_t a[2][4];
            #pragma unroll
            for (int mi = 0; mi < 2; mi++) {
                int mr = wm*32 + mi*16;
                a[mi][0] = __float_as_uint(As[(mr+g  )*36 + kk*8 + q    ]);
                a[mi][1] = __float_as_uint(As[(mr+g+8)*36 + kk*8 + q    ]);
                a[mi][2] = __float_as_uint(As[(mr+g  )*36 + kk*8 + q + 4]);
                a[mi][3] = __float_as_uint(As[(mr+g+8)*36 + kk*8 + q + 4]);
            }
            #pragma unroll
            for (int nf = 0; nf < 8; nf++) {
                uint32_t b[2];
                int nr = wn*64 + nf*8 + g;
                b[0] = __float_as_uint(Bs[nr*36 + kk*8 + q    ]);
                b[1] = __float_as_uint(Bs[nr*36 + kk*8 + q + 4]);
                mma8(acc[0][nf], a[0], b);
                mma8(acc[1][nf], a[1], b);
            }
        }
    }

    #pragma unroll
    for (int mi = 0; mi < 2; mi++) {
        size_t row0 = (size_t)(mt + wm*32 + mi*16 + g    ) * E_D + nt;
        size_t row1 = (size_t)(mt + wm*32 + mi*16 + g + 8) * E_D + nt;
        #pragma unroll
        for (int nf = 0; nf < 8; nf++) {
            int c = wn*64 + nf*8 + 2*q;
            float2 bb = *(const float2*)&bo[nt + c];
            *(float2*)&out[row0 + c] =
                make_float2(acc[mi][nf][0] + bb.x, acc[mi][nf][1] + bb.y);
            *(float2*)&out[row1 + c] =
                make_float2(acc[mi][nf][2] + bb.x, acc[mi][nf][3] + bb.y);
        }
    }
}

// ============================================================================
extern "C" void kernel_launch(void* const* d_in, const int* in_sizes, int n_in,
                              void* d_out, int out_size)
{
    const float* values = (const float*)d_in[0];
    const float* keysp  = (const float*)d_in[1];
    const float* query  = (const float*)d_in[2];
    const int*   mask   = (const int*)  d_in[3];
    const float* Wv     = (const float*)d_in[4];
    const float* Wk     = (const float*)d_in[5];
    const float* Wq     = (const float*)d_in[6];
    const float* Wo     = (const float*)d_in[7];
    const float* bo     = (const float*)d_in[8];
    float* out = (float*)d_out;

    // 0. pre-round Wo to TF32
    cvt_wo_kernel<<<E_D*E_D/4/256, 256>>>(Wo);

    // 1. QKV projections (outputs pre-rounded)
    proj_mma<<<dim3((N_B*L_S*H_N)/64, 3), 128>>>(values, keysp, query, Wv, Wk, Wq);

    // 2. flash attention (dynamic smem ~71 KB; attribute set is capture-safe)
    int smem = (64*KS_STRIDE + 64*VS_STRIDE + 128*SS_STRIDE + 3*128 + 64)
               * (int)sizeof(float);
    cudaFuncSetAttribute(attn_mma,
                         cudaFuncAttributeMaxDynamicSharedMemorySize, smem);
    attn_mma<<<dim3(L_S/128, H_N, N_B), 256, smem>>>(mask);

    // 3. output projection + bias (zero-cvt mainloop)
    out_gemm_mma<<<dim3(E_D/128, (N_B*L_S)/128), 256>>>(bo, out);
}

// round 4
// speedup vs baseline: 3.2524x; 1.0804x over previous
#include <cuda_runtime.h>
#include <cstdint>
#include <cstddef>

#define N_B 2
#define L_S 2048
#define E_D 1024
#define H_N 16
#define D_H 64
#define L2E 1.44269504088896341f

// -------- scratch (device globals; no allocations allowed) --------
// All hold TF32-pre-rounded values.
__device__ float g_q [N_B*H_N*L_S*D_H];   // [n][h][l][d]
__device__ float g_k [N_B*H_N*L_S*D_H];
__device__ float g_v [N_B*H_N*L_S*D_H];
__device__ float g_ao[N_B*L_S*E_D];       // attention output [n*L+l][E]
__device__ float g_wo[E_D*E_D];           // Wo, TF32-rounded

// ---------------- helpers ----------------
__device__ __forceinline__ uint32_t f2tf(float f) {
    uint32_t u; asm("cvt.rna.tf32.f32 %0, %1;" : "=r"(u) : "f"(f)); return u;
}
__device__ __forceinline__ float f2tf_f(float f) { return __uint_as_float(f2tf(f)); }
__device__ __forceinline__ float ex2(float x) {
    float y; asm("ex2.approx.f32 %0, %1;" : "=f"(y) : "f"(x)); return y;
}
__device__ __forceinline__ void mma8(float* d, const uint32_t* a, const uint32_t* b) {
    asm("mma.sync.aligned.m16n8k8.row.col.f32.tf32.tf32.f32 "
        "{%0,%1,%2,%3},{%4,%5,%6,%7},{%8,%9},{%0,%1,%2,%3};"
        : "+f"(d[0]), "+f"(d[1]), "+f"(d[2]), "+f"(d[3])
        : "r"(a[0]), "r"(a[1]), "r"(a[2]), "r"(a[3]),
          "r"(b[0]), "r"(b[1]));
}
__device__ __forceinline__ void cp16(uint32_t dst, const void* src) {
    asm volatile("cp.async.ca.shared.global [%0], [%1], 16;" :: "r"(dst), "l"(src));
}
#define CP_COMMIT() asm volatile("cp.async.commit_group;")
#define CP_WAIT0()  asm volatile("cp.async.wait_group 0;")
// Fragment maps (m16n8k8 tf32), g=lane>>2, q=lane&3:
//  A: a0=(g,q) a1=(g+8,q) a2=(g,q+4) a3=(g+8,q+4)
//  B: b0=(k=q, n=g) b1=(k=q+4, n=g)
//  C: c0=(g,2q) c1=(g,2q+1) c2=(g+8,2q) c3=(g+8,2q+1)

// ============================================================================
// Kernel 0: one-time TF32 rounding of Wo
// ============================================================================
__global__ __launch_bounds__(256) void cvt_wo_kernel(const float* __restrict__ Wo)
{
    int i = blockIdx.x * 256 + threadIdx.x;
    float4 v = ((const float4*)Wo)[i];
    v.x = f2tf_f(v.x); v.y = f2tf_f(v.y); v.z = f2tf_f(v.z); v.w = f2tf_f(v.w);
    ((float4*)g_wo)[i] = v;
}

// ============================================================================
// Kernel 1: QKV projection via mma; outputs TF32-pre-rounded.
// ============================================================================
__global__ __launch_bounds__(128) void proj_mma(
    const float* __restrict__ vals, const float* __restrict__ keys,
    const float* __restrict__ qry,
    const float* __restrict__ Wv, const float* __restrict__ Wk,
    const float* __restrict__ Wq)
{
    const float* X; const float* W; float* Y;
    int which = blockIdx.y;
    if (which == 0)      { X = vals; W = Wv; Y = g_v; }
    else if (which == 1) { X = keys; W = Wk; Y = g_k; }
    else                 { X = qry;  W = Wq; Y = g_q; }

    __shared__ float Xs[64*68];
    __shared__ float Ws[64*68];

    int rowBase = blockIdx.x * 64;
    int tid = threadIdx.x, warp = tid >> 5, lane = tid & 31;
    int g = lane >> 2, q = lane & 3;

    const float4* Xg = (const float4*)(X + (size_t)rowBase * 64);
    const float4* Wg = (const float4*)W;
    for (int i = tid; i < 1024; i += 128) {
        int r = i >> 4, c4 = (i & 15) << 2;
        *(float4*)&Xs[r*68 + c4] = Xg[i];
        *(float4*)&Ws[r*68 + c4] = Wg[i];
    }
    __syncthreads();

    int m0 = warp * 16;
    uint32_t a[8][4];
    #pragma unroll
    for (int kk = 0; kk < 8; kk++) {
        a[kk][0] = f2tf(Xs[(m0+g  )*68 + kk*8 + q    ]);
        a[kk][1] = f2tf(Xs[(m0+g+8)*68 + kk*8 + q    ]);
        a[kk][2] = f2tf(Xs[(m0+g  )*68 + kk*8 + q + 4]);
        a[kk][3] = f2tf(Xs[(m0+g+8)*68 + kk*8 + q + 4]);
    }

    float acc[8][4];
    #pragma unroll
    for (int nf = 0; nf < 8; nf++)
        #pragma unroll
        for (int t = 0; t < 4; t++) acc[nf][t] = 0.f;

    #pragma unroll
    for (int kk = 0; kk < 8; kk++) {
        #pragma unroll
        for (int nf = 0; nf < 8; nf++) {
            uint32_t b[2];
            b[0] = f2tf(Ws[(nf*8+g)*68 + kk*8 + q    ]);
            b[1] = f2tf(Ws[(nf*8+g)*68 + kk*8 + q + 4]);
            mma8(acc[nf], a[kk], b);
        }
    }

    int r0 = rowBase + m0 + g;
    int r1 = r0 + 8;
    int h0 = r0 & 15, nl0 = r0 >> 4;
    int h1 = r1 & 15, nl1 = r1 >> 4;
    size_t base0 = (((size_t)((nl0 >> 11)*H_N + h0))*L_S + (nl0 & (L_S-1)))*D_H;
    size_t base1 = (((size_t)((nl1 >> 11)*H_N + h1))*L_S + (nl1 & (L_S-1)))*D_H;
    #pragma unroll
    for (int nf = 0; nf < 8; nf++) {
        int c = nf*8 + 2*q;
        *(float2*)&Y[base0 + c] = make_float2(f2tf_f(acc[nf][0]), f2tf_f(acc[nf][1]));
        *(float2*)&Y[base1 + c] = make_float2(f2tf_f(acc[nf][2]), f2tf_f(acc[nf][3]));
    }
}

// ============================================================================
// Kernel 2: flash attention. q-tile 128, 256 threads (8 warps, m16 strip each).
// Warp-local register softmax (rows never cross warps), double-buffered K/V
// via cp.async, P staged per-warp (syncwarp only).
// ============================================================================
#define KSTR 68
#define VSTR 72
#define PSTR 68

__global__ __launch_bounds__(256) void attn_mma(const int* __restrict__ mask)
{
    extern __shared__ float sm[];
    float* Ksb = sm;                    // [2][64*KSTR]
    float* Vsb = sm + 2*64*KSTR;        // [2][64*VSTR]
    float* Ps  = Vsb + 2*64*VSTR;       // [128*PSTR] (per-warp 16-row strips; Q staging)

    int qt = blockIdx.x, h = blockIdx.y, n = blockIdx.z;
    int tid = threadIdx.x, warp = tid >> 5, lane = tid & 31;
    int g = lane >> 2, q = lane & 3;
    int m0 = warp * 16;

    const float* Qg = g_q + ((size_t)(n*H_N + h) * L_S + qt*128) * D_H;
    const float* Kg = g_k +  (size_t)(n*H_N + h) * L_S * D_H;
    const float* Vg = g_v +  (size_t)(n*H_N + h) * L_S * D_H;
    const int2*  mk2 = (const int2*)(mask + n * L_S);

    uint32_t ks_u = (uint32_t)__cvta_generic_to_shared(Ksb);
    uint32_t vs_u = (uint32_t)__cvta_generic_to_shared(Vsb);

    // prefetch K/V tile 0
    {
        const float4* K4 = (const float4*)Kg;
        const float4* V4 = (const float4*)Vg;
        for (int i = tid; i < 1024; i += 256) {
            int r = i >> 4, c4 = (i & 15) << 2;
            cp16(ks_u + (r*KSTR + c4)*4, K4 + i);
            cp16(vs_u + (r*VSTR + c4)*4, V4 + i);
        }
        CP_COMMIT();
    }

    // stage Q (128x64) into Ps
    for (int i = tid; i < 2048; i += 256) {
        int r = i >> 4, c4 = (i & 15) << 2;
        *(float4*)&Ps[r*PSTR + c4] = ((const float4*)Qg)[i];
    }
    __syncthreads();

    uint32_t qa[8][4];
    #pragma unroll
    for (int kk = 0; kk < 8; kk++) {
        qa[kk][0] = __float_as_uint(Ps[(m0+g  )*PSTR + kk*8 + q    ]);
        qa[kk][1] = __float_as_uint(Ps[(m0+g+8)*PSTR + kk*8 + q    ]);
        qa[kk][2] = __float_as_uint(Ps[(m0+g  )*PSTR + kk*8 + q + 4]);
        qa[kk][3] = __float_as_uint(Ps[(m0+g+8)*PSTR + kk*8 + q + 4]);
    }

    float O[8][4];
    #pragma unroll
    for (int nf = 0; nf < 8; nf++)
        #pragma unroll
        for (int t = 0; t < 4; t++) O[nf][t] = 0.f;
    float mr0 = -3.0e38f, mr1 = -3.0e38f, lr0 = 0.f, lr1 = 0.f;

    for (int kt = 0; kt < L_S/64; kt++) {
        CP_WAIT0();
        __syncthreads();          // tile kt visible to all; prev buffer free

        if (kt + 1 < L_S/64) {    // prefetch kt+1 into other buffer
            const float4* K4 = (const float4*)(Kg + (size_t)(kt+1) * 4096);
            const float4* V4 = (const float4*)(Vg + (size_t)(kt+1) * 4096);
            uint32_t ko = ks_u + ((kt+1)&1) * 64*KSTR*4;
            uint32_t vo = vs_u + ((kt+1)&1) * 64*VSTR*4;
            for (int i = tid; i < 1024; i += 256) {
                int r = i >> 4, c4 = (i & 15) << 2;
                cp16(ko + (r*KSTR + c4)*4, K4 + i);
                cp16(vo + (r*VSTR + c4)*4, V4 + i);
            }
            CP_COMMIT();
        }
        const float* Ks = Ksb + (kt&1) * 64*KSTR;
        const float* Vs = Vsb + (kt&1) * 64*VSTR;

        // ---- S = Q K^T ----
        float sacc[8][4];
        #pragma unroll
        for (int nf = 0; nf < 8; nf++)
            #pragma unroll
            for (int t = 0; t < 4; t++) sacc[nf][t] = 0.f;

        #pragma unroll
        for (int kk = 0; kk < 8; kk++) {
            #pragma unroll
            for (int nf = 0; nf < 8; nf++) {
                uint32_t b[2];
                b[0] = __float_as_uint(Ks[(nf*8+g)*KSTR + kk*8 + q    ]);
                b[1] = __float_as_uint(Ks[(nf*8+g)*KSTR + kk*8 + q + 4]);
                mma8(sacc[nf], qa[kk], b);
            }
        }

        // ---- mask + scale (1/32) + row max, all in registers ----
        float rmax0 = -3.0e38f, rmax1 = -3.0e38f;
        #pragma unroll
        for (int nf = 0; nf < 8; nf++) {
            int2 mm = __ldg(&mk2[kt*32 + nf*4 + q]);
            float s0 = mm.x ? sacc[nf][0]*0.03125f : -1.0e30f;
            float s1 = mm.y ? sacc[nf][1]*0.03125f : -1.0e30f;
            float s2 = mm.x ? sacc[nf][2]*0.03125f : -1.0e30f;
            float s3 = mm.y ? sacc[nf][3]*0.03125f : -1.0e30f;
            sacc[nf][0] = s0; sacc[nf][1] = s1; sacc[nf][2] = s2; sacc[nf][3] = s3;
            rmax0 = fmaxf(rmax0, fmaxf(s0, s1));
            rmax1 = fmaxf(rmax1, fmaxf(s2, s3));
        }
        rmax0 = fmaxf(rmax0, __shfl_xor_sync(0xffffffffu, rmax0, 1));
        rmax0 = fmaxf(rmax0, __shfl_xor_sync(0xffffffffu, rmax0, 2));
        rmax1 = fmaxf(rmax1, __shfl_xor_sync(0xffffffffu, rmax1, 1));
        rmax1 = fmaxf(rmax1, __shfl_xor_sync(0xffffffffu, rmax1, 2));

        float mnew0 = fmaxf(mr0, rmax0);
        float mnew1 = fmaxf(mr1, rmax1);
        float cr0 = ex2((mr0 - mnew0) * L2E);
        float cr1 = ex2((mr1 - mnew1) * L2E);

        // ---- exp + P store (TF32-rounded) + row sum ----
        float psum0 = 0.f, psum1 = 0.f;
        #pragma unroll
        for (int nf = 0; nf < 8; nf++) {
            float p0 = ex2((sacc[nf][0] - mnew0) * L2E);
            float p1 = ex2((sacc[nf][1] - mnew0) * L2E);
            float p2 = ex2((sacc[nf][2] - mnew1) * L2E);
            float p3 = ex2((sacc[nf][3] - mnew1) * L2E);
            psum0 += p0 + p1;
            psum1 += p2 + p3;
            int c = nf*8 + 2*q;
            *(float2*)&Ps[(m0+g  )*PSTR + c] = make_float2(f2tf_f(p0), f2tf_f(p1));
            *(float2*)&Ps[(m0+g+8)*PSTR + c] = make_float2(f2tf_f(p2), f2tf_f(p3));
        }
        psum0 += __shfl_xor_sync(0xffffffffu, psum0, 1);
        psum0 += __shfl_xor_sync(0xffffffffu, psum0, 2);
        psum1 += __shfl_xor_sync(0xffffffffu, psum1, 1);
        psum1 += __shfl_xor_sync(0xffffffffu, psum1, 2);

        lr0 = lr0 * cr0 + psum0;  mr0 = mnew0;
        lr1 = lr1 * cr1 + psum1;  mr1 = mnew1;

        #pragma unroll
        for (int nf = 0; nf < 8; nf++) {
            O[nf][0] *= cr0; O[nf][1] *= cr0;
            O[nf][2] *= cr1; O[nf][3] *= cr1;
        }
        __syncwarp();   // P strip visible within warp

        // ---- O += P @ V ----
        #pragma unroll
        for (int ck = 0; ck < 8; ck++) {
            uint32_t pa[4];
            pa[0] = __float_as_uint(Ps[(m0+g  )*PSTR + ck*8 + q    ]);
            pa[1] = __float_as_uint(Ps[(m0+g+8)*PSTR + ck*8 + q    ]);
            pa[2] = __float_as_uint(Ps[(m0+g  )*PSTR + ck*8 + q + 4]);
            pa[3] = __float_as_uint(Ps[(m0+g+8)*PSTR + ck*8 + q + 4]);
            #pragma unroll
            for (int nf = 0; nf < 8; nf++) {
                uint32_t b[2];
                b[0] = __float_as_uint(Vs[(ck*8 + q    )*VSTR + nf*8 + g]);
                b[1] = __float_as_uint(Vs[(ck*8 + q + 4)*VSTR + nf*8 + g]);
                mma8(O[nf], pa, b);
            }
        }
        // next iteration's __syncthreads orders the next P store after these reads
    }

    // ---- epilogue: divide by row sum, store TF32-pre-rounded ----
    float invl0 = 1.0f / lr0;
    float invl1 = 1.0f / lr1;
    size_t row0 = ((size_t)n*L_S + qt*128 + m0 + g    ) * E_D + h*D_H;
    size_t row1 = ((size_t)n*L_S + qt*128 + m0 + g + 8) * E_D + h*D_H;
    #pragma unroll
    for (int nf = 0; nf < 8; nf++) {
        int c = nf*8 + 2*q;
        *(float2*)&g_ao[row0 + c] =
            make_float2(f2tf_f(O[nf][0]*invl0), f2tf_f(O[nf][1]*invl0));
        *(float2*)&g_ao[row1 + c] =
            make_float2(f2tf_f(O[nf][2]*invl1), f2tf_f(O[nf][3]*invl1));
    }
}

// ============================================================================
// Kernel 3: out = A @ Wo^T + bo, double-buffered cp.async.
// 128x128 tile, BK=32, 256 threads (8 warps: 4m x 2n, warp tile m32 x n64).
// ============================================================================
__global__ __launch_bounds__(256) void out_gemm_mma(
    const float* __restrict__ bo, float* __restrict__ out)
{
    extern __shared__ float sm[];
    float* As = sm;              // [2][128*36]
    float* Bs = sm + 2*128*36;   // [2][128*36]

    int nt = blockIdx.x * 128;
    int mt = blockIdx.y * 128;
    int tid = threadIdx.x, warp = tid >> 5, lane = tid & 31;
    int g = lane >> 2, q = lane & 3;
    int wm = warp & 3, wn = warp >> 2;

    uint32_t as_u = (uint32_t)__cvta_generic_to_shared(As);
    uint32_t bs_u = (uint32_t)__cvta_generic_to_shared(Bs);

    float acc[2][8][4];
    #pragma unroll
    for (int mi = 0; mi < 2; mi++)
        #pragma unroll
        for (int nf = 0; nf < 8; nf++)
            #pragma unroll
            for (int t = 0; t < 4; t++) acc[mi][nf][t] = 0.f;

    // prefetch tile 0
    for (int i = tid; i < 2048; i += 256) {
        int i2 = i & 1023;
        int r = i2 >> 3, c4 = (i2 & 7) << 2;
        if (i < 1024) cp16(as_u + (r*36 + c4)*4, &g_ao[(size_t)(mt + r)*E_D + c4]);
        else          cp16(bs_u + (r*36 + c4)*4, &g_wo[(size_t)(nt + r)*E_D + c4]);
    }
    CP_COMMIT();

    for (int t = 0; t < E_D/32; t++) {
        CP_WAIT0();
        __syncthreads();

        if (t + 1 < E_D/32) {
            int kt = (t + 1) * 32;
            uint32_t ao = as_u + ((t+1)&1) * 128*36*4;
            uint32_t bo_u = bs_u + ((t+1)&1) * 128*36*4;
            for (int i = tid; i < 2048; i += 256) {
                int i2 = i & 1023;
                int r = i2 >> 3, c4 = (i2 & 7) << 2;
                if (i < 1024) cp16(ao  + (r*36 + c4)*4, &g_ao[(size_t)(mt + r)*E_D + kt + c4]);
                else          cp16(bo_u + (r*36 + c4)*4, &g_wo[(size_t)(nt + r)*E_D + kt + c4]);
            }
            CP_COMMIT();
        }
        const float* Ac = As + (t&1) * 128*36;
        const float* Bc = Bs + (t&1) * 128*36;

        #pragma unroll
        for (int kk = 0; kk < 4; kk++) {
            uint32_t a[2][4];
            #pragma unroll
            for (int mi = 0; mi < 2; mi++) {
                int mr = wm*32 + mi*16;
                a[mi][0] = __float_as_uint(Ac[(mr+g  )*36 + kk*8 + q    ]);
                a[mi][1] = __float_as_uint(Ac[(mr+g+8)*36 + kk*8 + q    ]);
                a[mi][2] = __float_as_uint(Ac[(mr+g  )*36 + kk*8 + q + 4]);
                a[mi][3] = __float_as_uint(Ac[(mr+g+8)*36 + kk*8 + q + 4]);
            }
            #pragma unroll
            for (int nf = 0; nf < 8; nf++) {
                uint32_t b[2];
                int nr = wn*64 + nf*8 + g;
                b[0] = __float_as_uint(Bc[nr*36 + kk*8 + q    ]);
                b[1] = __float_as_uint(Bc[nr*36 + kk*8 + q + 4]);
                mma8(acc[0][nf], a[0], b);
                mma8(acc[1][nf], a[1], b);
            }
        }
    }

    #pragma unroll
    for (int mi = 0; mi < 2; mi++) {
        size_t row0 = (size_t)(mt + wm*32 + mi*16 + g    ) * E_D + nt;
        size_t row1 = (size_t)(mt + wm*32 + mi*16 + g + 8) * E_D + nt;
        #pragma unroll
        for (int nf = 0; nf < 8; nf++) {
            int c = wn*64 + nf*8 + 2*q;
            float2 bb = *(const float2*)&bo[nt + c];
            *(float2*)&out[row0 + c] =
                make_float2(acc[mi][nf][0] + bb.x, acc[mi][nf][1] + bb.y);
            *(float2*)&out[row1 + c] =
                make_float2(acc[mi][nf][2] + bb.x, acc[mi][nf][3] + bb.y);
        }
    }
}

// ============================================================================
extern "C" void kernel_launch(void* const* d_in, const int* in_sizes, int n_in,
                              void* d_out, int out_size)
{
    const float* values = (const float*)d_in[0];
    const float* keysp  = (const float*)d_in[1];
    const float* query  = (const float*)d_in[2];
    const int*   mask   = (const int*)  d_in[3];
    const float* Wv     = (const float*)d_in[4];
    const float* Wk     = (const float*)d_in[5];
    const float* Wq     = (const float*)d_in[6];
    const float* Wo     = (const float*)d_in[7];
    const float* bo     = (const float*)d_in[8];
    float* out = (float*)d_out;

    // 0. pre-round Wo to TF32
    cvt_wo_kernel<<<E_D*E_D/4/256, 256>>>(Wo);

    // 1. QKV projections (outputs pre-rounded)
    proj_mma<<<dim3((N_B*L_S*H_N)/64, 3), 128>>>(values, keysp, query, Wv, Wk, Wq);

    // 2. flash attention (double-buffered K/V; ~104 KB dynamic smem)
    int smem_attn = (2*64*KSTR + 2*64*VSTR + 128*PSTR) * (int)sizeof(float);
    cudaFuncSetAttribute(attn_mma,
                         cudaFuncAttributeMaxDynamicSharedMemorySize, smem_attn);
    attn_mma<<<dim3(L_S/128, H_N, N_B), 256, smem_attn>>>(mask);

    // 3. output projection + bias (double-buffered; 72 KB dynamic smem)
    int smem_og = 4*128*36 * (int)sizeof(float);
    cudaFuncSetAttribute(out_gemm_mma,
                         cudaFuncAttributeMaxDynamicSharedMemorySize, smem_og);
    out_gemm_mma<<<dim3(E_D/128, (N_B*L_S)/128), 256, smem_og>>>(bo, out);
}

// round 5
// speedup vs baseline: 3.9022x; 1.1998x over previous
#include <cuda_runtime.h>
#include <cstdint>
#include <cstddef>

#define N_B 2
#define L_S 2048
#define E_D 1024
#define H_N 16
#define D_H 64
#define L2E 1.44269504088896341f

// -------- scratch (device globals; no allocations allowed) --------
// All hold TF32-pre-rounded values.
__device__ float g_q [N_B*H_N*L_S*D_H];   // [n][h][l][d]
__device__ float g_k [N_B*H_N*L_S*D_H];
__device__ float g_v [N_B*H_N*L_S*D_H];
__device__ float g_ao[N_B*L_S*E_D];       // attention output [n*L+l][E]
__device__ float g_wo[E_D*E_D];           // Wo, TF32-rounded
__device__ float g_wq[D_H*D_H];           // Wq/Wk/Wv, TF32-rounded
__device__ float g_wk[D_H*D_H];
__device__ float g_wv[D_H*D_H];

// ---------------- helpers ----------------
__device__ __forceinline__ uint32_t f2tf(float f) {
    uint32_t u; asm("cvt.rna.tf32.f32 %0, %1;" : "=r"(u) : "f"(f)); return u;
}
__device__ __forceinline__ float f2tf_f(float f) { return __uint_as_float(f2tf(f)); }
__device__ __forceinline__ float ex2(float x) {
    float y; asm("ex2.approx.f32 %0, %1;" : "=f"(y) : "f"(x)); return y;
}
__device__ __forceinline__ void mma8(float* d, const uint32_t* a, const uint32_t* b) {
    asm("mma.sync.aligned.m16n8k8.row.col.f32.tf32.tf32.f32 "
        "{%0,%1,%2,%3},{%4,%5,%6,%7},{%8,%9},{%0,%1,%2,%3};"
        : "+f"(d[0]), "+f"(d[1]), "+f"(d[2]), "+f"(d[3])
        : "r"(a[0]), "r"(a[1]), "r"(a[2]), "r"(a[3]),
          "r"(b[0]), "r"(b[1]));
}
__device__ __forceinline__ void cp16(uint32_t dst, const void* src) {
    asm volatile("cp.async.ca.shared.global [%0], [%1], 16;" :: "r"(dst), "l"(src));
}
#define CP_COMMIT() asm volatile("cp.async.commit_group;")
#define CP_WAIT0()  asm volatile("cp.async.wait_group 0;")
// Fragment maps (m16n8k8 tf32), g=lane>>2, q=lane&3:
//  A: a0=(g,q) a1=(g+8,q) a2=(g,q+4) a3=(g+8,q+4)
//  B: b0=(k=q, n=g) b1=(k=q+4, n=g)
//  C: c0=(g,2q) c1=(g,2q+1) c2=(g+8,2q) c3=(g+8,2q+1)

// ============================================================================
// Kernel 0a: TF32 rounding of Wo
// ============================================================================
__global__ __launch_bounds__(256) void cvt_wo_kernel(const float* __restrict__ Wo)
{
    int i = blockIdx.x * 256 + threadIdx.x;
    float4 v = ((const float4*)Wo)[i];
    v.x = f2tf_f(v.x); v.y = f2tf_f(v.y); v.z = f2tf_f(v.z); v.w = f2tf_f(v.w);
    ((float4*)g_wo)[i] = v;
}

// Kernel 0b: TF32 rounding of Wq/Wk/Wv (each 4096 floats = 1024 float4)
__global__ __launch_bounds__(256) void cvt_wqkv_kernel(
    const float* __restrict__ Wq, const float* __restrict__ Wk,
    const float* __restrict__ Wv)
{
    int i = blockIdx.x * 256 + threadIdx.x;   // 0..3071
    int which = i >> 10, j = i & 1023;
    const float4* src = (const float4*)(which == 0 ? Wq : (which == 1 ? Wk : Wv));
    float4* dst = (float4*)(which == 0 ? g_wq : (which == 1 ? g_wk : g_wv));
    float4 v = src[j];
    v.x = f2tf_f(v.x); v.y = f2tf_f(v.y); v.z = f2tf_f(v.z); v.w = f2tf_f(v.w);
    dst[j] = v;
}

// ============================================================================
// Kernel 1: QKV projection. 256 rows/block, 256 threads (8 warps = 4m x 2n).
// W fragments live in registers (pre-rounded from g_w*); X pipelined cp.async.
// ============================================================================
__global__ __launch_bounds__(256) void proj_mma(
    const float* __restrict__ vals, const float* __restrict__ keys,
    const float* __restrict__ qry)
{
    const float* X; const float* Wc; float* Y;
    int which = blockIdx.y;
    if (which == 0)      { X = vals; Wc = g_wv; Y = g_v; }
    else if (which == 1) { X = keys; Wc = g_wk; Y = g_k; }
    else                 { X = qry;  Wc = g_wq; Y = g_q; }

    __shared__ float Xs[2][64*68];

    int rowBase0 = blockIdx.x * 256;
    int tid = threadIdx.x, warp = tid >> 5, lane = tid & 31;
    int g = lane >> 2, q = lane & 3;
    int wm = warp & 3, wn = warp >> 2;

    // W B-fragments in registers: n-cols wn*32..wn*32+31 (nf2 = 0..3)
    uint32_t wb[8][4][2];
    #pragma unroll
    for (int kk = 0; kk < 8; kk++)
        #pragma unroll
        for (int nf2 = 0; nf2 < 4; nf2++) {
            int nn = wn*32 + nf2*8 + g;
            wb[kk][nf2][0] = __float_as_uint(__ldg(&Wc[nn*64 + kk*8 + q    ]));
            wb[kk][nf2][1] = __float_as_uint(__ldg(&Wc[nn*64 + kk*8 + q + 4]));
        }

    uint32_t xs_u = (uint32_t)__cvta_generic_to_shared(Xs);

    // prefetch X tile 0 (64 rows x 64)
    {
        const float4* Xg = (const float4*)(X + (size_t)rowBase0 * 64);
        for (int i = tid; i < 1024; i += 256) {
            int r = i >> 4, c4 = (i & 15) << 2;
            cp16(xs_u + (r*68 + c4)*4, Xg + i);
        }
        CP_COMMIT();
    }

    for (int rt = 0; rt < 4; rt++) {
        CP_WAIT0();
        __syncthreads();

        if (rt + 1 < 4) {
            const float4* Xg = (const float4*)(X + (size_t)(rowBase0 + (rt+1)*64) * 64);
            uint32_t xo = xs_u + ((rt+1)&1) * 64*68*4;
            for (int i = tid; i < 1024; i += 256) {
                int r = i >> 4, c4 = (i & 15) << 2;
                cp16(xo + (r*68 + c4)*4, Xg + i);
            }
            CP_COMMIT();
        }
        const float* Xc = Xs[rt & 1];

        float acc[4][4];
        #pragma unroll
        for (int nf2 = 0; nf2 < 4; nf2++)
            #pragma unroll
            for (int t = 0; t < 4; t++) acc[nf2][t] = 0.f;

        #pragma unroll
        for (int kk = 0; kk < 8; kk++) {
            uint32_t a[4];
            a[0] = f2tf(Xc[(wm*16+g  )*68 + kk*8 + q    ]);
            a[1] = f2tf(Xc[(wm*16+g+8)*68 + kk*8 + q    ]);
            a[2] = f2tf(Xc[(wm*16+g  )*68 + kk*8 + q + 4]);
            a[3] = f2tf(Xc[(wm*16+g+8)*68 + kk*8 + q + 4]);
            #pragma unroll
            for (int nf2 = 0; nf2 < 4; nf2++)
                mma8(acc[nf2], a, wb[kk][nf2]);
        }

        // scatter-store pre-rounded: row ri -> (n,h,l)
        int r0 = rowBase0 + rt*64 + wm*16 + g;
        int r1 = r0 + 8;
        int h0 = r0 & 15, nl0 = r0 >> 4;
        int h1 = r1 & 15, nl1 = r1 >> 4;
        size_t base0 = (((size_t)((nl0 >> 11)*H_N + h0))*L_S + (nl0 & (L_S-1)))*D_H;
        size_t base1 = (((size_t)((nl1 >> 11)*H_N + h1))*L_S + (nl1 & (L_S-1)))*D_H;
        #pragma unroll
        for (int nf2 = 0; nf2 < 4; nf2++) {
            int c = wn*32 + nf2*8 + 2*q;
            *(float2*)&Y[base0 + c] = make_float2(f2tf_f(acc[nf2][0]), f2tf_f(acc[nf2][1]));
            *(float2*)&Y[base1 + c] = make_float2(f2tf_f(acc[nf2][2]), f2tf_f(acc[nf2][3]));
        }
    }
}

// ============================================================================
// Kernel 2: flash attention. q-tile 128, 128 threads (4 warps, m32 strips).
// K/V B-fragments shared across both m16 sub-strips -> 1.25 LDS per mma.
// Register softmax; double-buffered K/V via cp.async.
// ============================================================================
#define KSTR 68
#define VSTR 72
#define PSTR 68

__global__ __launch_bounds__(128) void attn_mma(const int* __restrict__ mask)
{
    extern __shared__ float sm[];
    float* Ksb = sm;                    // [2][64*KSTR]
    float* Vsb = sm + 2*64*KSTR;        // [2][64*VSTR]
    float* Ps  = Vsb + 2*64*VSTR;       // [128*PSTR] (warp-private 32-row strips)

    int qt = blockIdx.x, h = blockIdx.y, n = blockIdx.z;
    int tid = threadIdx.x, warp = tid >> 5, lane = tid & 31;
    int g = lane >> 2, q = lane & 3;
    int m0 = warp * 32;

    const float* Qg = g_q + ((size_t)(n*H_N + h) * L_S + qt*128) * D_H;
    const float* Kg = g_k +  (size_t)(n*H_N + h) * L_S * D_H;
    const float* Vg = g_v +  (size_t)(n*H_N + h) * L_S * D_H;
    const int2*  mk2 = (const int2*)(mask + n * L_S);

    uint32_t ks_u = (uint32_t)__cvta_generic_to_shared(Ksb);
    uint32_t vs_u = (uint32_t)__cvta_generic_to_shared(Vsb);

    // prefetch K/V tile 0
    {
        const float4* K4 = (const float4*)Kg;
        const float4* V4 = (const float4*)Vg;
        for (int i = tid; i < 1024; i += 128) {
            int r = i >> 4, c4 = (i & 15) << 2;
            cp16(ks_u + (r*KSTR + c4)*4, K4 + i);
            cp16(vs_u + (r*VSTR + c4)*4, V4 + i);
        }
        CP_COMMIT();
    }

    // stage Q (128x64) into Ps
    for (int i = tid; i < 2048; i += 128) {
        int r = i >> 4, c4 = (i & 15) << 2;
        *(float4*)&Ps[r*PSTR + c4] = ((const float4*)Qg)[i];
    }
    __syncthreads();

    uint32_t qa[2][8][4];
    #pragma unroll
    for (int mi = 0; mi < 2; mi++)
        #pragma unroll
        for (int kk = 0; kk < 8; kk++) {
            int mr = m0 + mi*16;
            qa[mi][kk][0] = __float_as_uint(Ps[(mr+g  )*PSTR + kk*8 + q    ]);
            qa[mi][kk][1] = __float_as_uint(Ps[(mr+g+8)*PSTR + kk*8 + q    ]);
            qa[mi][kk][2] = __float_as_uint(Ps[(mr+g  )*PSTR + kk*8 + q + 4]);
            qa[mi][kk][3] = __float_as_uint(Ps[(mr+g+8)*PSTR + kk*8 + q + 4]);
        }

    float O[2][8][4];
    #pragma unroll
    for (int mi = 0; mi < 2; mi++)
        #pragma unroll
        for (int nf = 0; nf < 8; nf++)
            #pragma unroll
            for (int t = 0; t < 4; t++) O[mi][nf][t] = 0.f;
    float mrow[2][2] = {{-3.0e38f,-3.0e38f},{-3.0e38f,-3.0e38f}};
    float lrow[2][2] = {{0.f,0.f},{0.f,0.f}};

    for (int kt = 0; kt < L_S/64; kt++) {
        CP_WAIT0();
        __syncthreads();          // tile kt visible; prev buffer free

        if (kt + 1 < L_S/64) {
            const float4* K4 = (const float4*)(Kg + (size_t)(kt+1) * 4096);
            const float4* V4 = (const float4*)(Vg + (size_t)(kt+1) * 4096);
            uint32_t ko = ks_u + ((kt+1)&1) * 64*KSTR*4;
            uint32_t vo = vs_u + ((kt+1)&1) * 64*VSTR*4;
            for (int i = tid; i < 1024; i += 128) {
                int r = i >> 4, c4 = (i & 15) << 2;
                cp16(ko + (r*KSTR + c4)*4, K4 + i);
                cp16(vo + (r*VSTR + c4)*4, V4 + i);
            }
            CP_COMMIT();
        }
        const float* Ks = Ksb + (kt&1) * 64*KSTR;
        const float* Vs = Vsb + (kt&1) * 64*VSTR;

        // ---- S = Q K^T : K frags shared across both strips ----
        float sacc[2][8][4];
        #pragma unroll
        for (int mi = 0; mi < 2; mi++)
            #pragma unroll
            for (int nf = 0; nf < 8; nf++)
                #pragma unroll
                for (int t = 0; t < 4; t++) sacc[mi][nf][t] = 0.f;

        #pragma unroll
        for (int kk = 0; kk < 8; kk++) {
            #pragma unroll
            for (int nf = 0; nf < 8; nf++) {
                uint32_t b[2];
                b[0] = __float_as_uint(Ks[(nf*8+g)*KSTR + kk*8 + q    ]);
                b[1] = __float_as_uint(Ks[(nf*8+g)*KSTR + kk*8 + q + 4]);
                mma8(sacc[0][nf], qa[0][kk], b);
                mma8(sacc[1][nf], qa[1][kk], b);
            }
        }

        // ---- mask + scale (1/32) + row max ----
        float rmax[2][2] = {{-3.0e38f,-3.0e38f},{-3.0e38f,-3.0e38f}};
        #pragma unroll
        for (int nf = 0; nf < 8; nf++) {
            int2 mm = __ldg(&mk2[kt*32 + nf*4 + q]);
            #pragma unroll
            for (int mi = 0; mi < 2; mi++) {
                float s0 = mm.x ? sacc[mi][nf][0]*0.03125f : -1.0e30f;
                float s1 = mm.y ? sacc[mi][nf][1]*0.03125f : -1.0e30f;
                float s2 = mm.x ? sacc[mi][nf][2]*0.03125f : -1.0e30f;
                float s3 = mm.y ? sacc[mi][nf][3]*0.03125f : -1.0e30f;
                sacc[mi][nf][0]=s0; sacc[mi][nf][1]=s1;
                sacc[mi][nf][2]=s2; sacc[mi][nf][3]=s3;
                rmax[mi][0] = fmaxf(rmax[mi][0], fmaxf(s0, s1));
                rmax[mi][1] = fmaxf(rmax[mi][1], fmaxf(s2, s3));
            }
        }
        float mnew[2][2], cr[2][2];
        #pragma unroll
        for (int mi = 0; mi < 2; mi++)
            #pragma unroll
            for (int hf = 0; hf < 2; hf++) {
                float v = rmax[mi][hf];
                v = fmaxf(v, __shfl_xor_sync(0xffffffffu, v, 1));
                v = fmaxf(v, __shfl_xor_sync(0xffffffffu, v, 2));
                mnew[mi][hf] = fmaxf(mrow[mi][hf], v);
                cr[mi][hf]   = ex2((mrow[mi][hf] - mnew[mi][hf]) * L2E);
            }

        // ---- exp + P store (TF32-rounded) + row sum ----
        float psum[2][2] = {{0.f,0.f},{0.f,0.f}};
        #pragma unroll
        for (int nf = 0; nf < 8; nf++) {
            int c = nf*8 + 2*q;
            #pragma unroll
            for (int mi = 0; mi < 2; mi++) {
                float p0 = ex2((sacc[mi][nf][0] - mnew[mi][0]) * L2E);
                float p1 = ex2((sacc[mi][nf][1] - mnew[mi][0]) * L2E);
                float p2 = ex2((sacc[mi][nf][2] - mnew[mi][1]) * L2E);
                float p3 = ex2((sacc[mi][nf][3] - mnew[mi][1]) * L2E);
                psum[mi][0] += p0 + p1;
                psum[mi][1] += p2 + p3;
                int mr = m0 + mi*16;
                *(float2*)&Ps[(mr+g  )*PSTR + c] = make_float2(f2tf_f(p0), f2tf_f(p1));
                *(float2*)&Ps[(mr+g+8)*PSTR + c] = make_float2(f2tf_f(p2), f2tf_f(p3));
            }
        }
        #pragma unroll
        for (int mi = 0; mi < 2; mi++)
            #pragma unroll
            for (int hf = 0; hf < 2; hf++) {
                float v = psum[mi][hf];
                v += __shfl_xor_sync(0xffffffffu, v, 1);
                v += __shfl_xor_sync(0xffffffffu, v, 2);
                lrow[mi][hf] = lrow[mi][hf] * cr[mi][hf] + v;
                mrow[mi][hf] = mnew[mi][hf];
            }

        #pragma unroll
        for (int mi = 0; mi < 2; mi++)
            #pragma unroll
            for (int nf = 0; nf < 8; nf++) {
                O[mi][nf][0] *= cr[mi][0]; O[mi][nf][1] *= cr[mi][0];
                O[mi][nf][2] *= cr[mi][1]; O[mi][nf][3] *= cr[mi][1];
            }
        __syncwarp();   // P strip visible within warp

        // ---- O += P @ V : V frags shared across both strips ----
        #pragma unroll
        for (int ck = 0; ck < 8; ck++) {
            uint32_t pa[2][4];
            #pragma unroll
            for (int mi = 0; mi < 2; mi++) {
                int mr = m0 + mi*16;
                pa[mi][0] = __float_as_uint(Ps[(mr+g  )*PSTR + ck*8 + q    ]);
                pa[mi][1] = __float_as_uint(Ps[(mr+g+8)*PSTR + ck*8 + q    ]);
                pa[mi][2] = __float_as_uint(Ps[(mr+g  )*PSTR + ck*8 + q + 4]);
                pa[mi][3] = __float_as_uint(Ps[(mr+g+8)*PSTR + ck*8 + q + 4]);
            }
            #pragma unroll
            for (int nf = 0; nf < 8; nf++) {
                uint32_t b[2];
                b[0] = __float_as_uint(Vs[(ck*8 + q    )*VSTR + nf*8 + g]);
                b[1] = __float_as_uint(Vs[(ck*8 + q + 4)*VSTR + nf*8 + g]);
                mma8(O[0][nf], pa[0], b);
                mma8(O[1][nf], pa[1], b);
            }
        }
    }

    // ---- epilogue ----
    #pragma unroll
    for (int mi = 0; mi < 2; mi++) {
        float invl0 = 1.0f / lrow[mi][0];
        float invl1 = 1.0f / lrow[mi][1];
        size_t row0 = ((size_t)n*L_S + qt*128 + m0 + mi*16 + g    ) * E_D + h*D_H;
        size_t row1 = ((size_t)n*L_S + qt*128 + m0 + mi*16 + g + 8) * E_D + h*D_H;
        #pragma unroll
        for (int nf = 0; nf < 8; nf++) {
            int c = nf*8 + 2*q;
            *(float2*)&g_ao[row0 + c] =
                make_float2(f2tf_f(O[mi][nf][0]*invl0), f2tf_f(O[mi][nf][1]*invl0));
            *(float2*)&g_ao[row1 + c] =
                make_float2(f2tf_f(O[mi][nf][2]*invl1), f2tf_f(O[mi][nf][3]*invl1));
        }
    }
}

// ============================================================================
// Kernel 3: out = A @ Wo^T + bo. 128x128 tile, BK=32, 128 threads
// (4 warps = 2m x 2n, warp tile m64 x n64 -> 1.0 LDS per mma).
// ============================================================================
__global__ __launch_bounds__(128) void out_gemm_mma(
    const float* __restrict__ bo, float* __restrict__ out)
{
    extern __shared__ float sm[];
    float* As = sm;              // [2][128*36]
    float* Bs = sm + 2*128*36;   // [2][128*36]

    int nt = blockIdx.x * 128;
    int mt = blockIdx.y * 128;
    int tid = threadIdx.x, warp = tid >> 5, lane = tid & 31;
    int g = lane >> 2, q = lane & 3;
    int wm = warp & 1, wn = warp >> 1;

    uint32_t as_u = (uint32_t)__cvta_generic_to_shared(As);
    uint32_t bs_u = (uint32_t)__cvta_generic_to_shared(Bs);

    float acc[4][8][4];
    #pragma unroll
    for (int mi = 0; mi < 4; mi++)
        #pragma unroll
        for (int nf = 0; nf < 8; nf++)
            #pragma unroll
            for (int t = 0; t < 4; t++) acc[mi][nf][t] = 0.f;

    // prefetch tile 0
    for (int i = tid; i < 2048; i += 128) {
        int i2 = i & 1023;
        int r = i2 >> 3, c4 = (i2 & 7) << 2;
        if (i < 1024) cp16(as_u + (r*36 + c4)*4, &g_ao[(size_t)(mt + r)*E_D + c4]);
        else          cp16(bs_u + (r*36 + c4)*4, &g_wo[(size_t)(nt + r)*E_D + c4]);
    }
    CP_COMMIT();

    for (int t = 0; t < E_D/32; t++) {
        CP_WAIT0();
        __syncthreads();

        if (t + 1 < E_D/32) {
            int kt = (t + 1) * 32;
            uint32_t ao  = as_u + ((t+1)&1) * 128*36*4;
            uint32_t bou = bs_u + ((t+1)&1) * 128*36*4;
            for (int i = tid; i < 2048; i += 128) {
                int i2 = i & 1023;
                int r = i2 >> 3, c4 = (i2 & 7) << 2;
                if (i < 1024) cp16(ao  + (r*36 + c4)*4, &g_ao[(size_t)(mt + r)*E_D + kt + c4]);
                else          cp16(bou + (r*36 + c4)*4, &g_wo[(size_t)(nt + r)*E_D + kt + c4]);
            }
            CP_COMMIT();
        }
        const float* Ac = As + (t&1) * 128*36;
        const float* Bc = Bs + (t&1) * 128*36;

        #pragma unroll
        for (int kk = 0; kk < 4; kk++) {
            uint32_t a[4][4];
            #pragma unroll
            for (int mi = 0; mi < 4; mi++) {
                int mr = wm*64 + mi*16;
                a[mi][0] = __float_as_uint(Ac[(mr+g  )*36 + kk*8 + q    ]);
                a[mi][1] = __float_as_uint(Ac[(mr+g+8)*36 + kk*8 + q    ]);
                a[mi][2] = __float_as_uint(Ac[(mr+g  )*36 + kk*8 + q + 4]);
                a[mi][3] = __float_as_uint(Ac[(mr+g+8)*36 + kk*8 + q + 4]);
            }
            #pragma unroll
            for (int nf = 0; nf < 8; nf++) {
                uint32_t b[2];
                int nr = wn*64 + nf*8 + g;
                b[0] = __float_as_uint(Bc[nr*36 + kk*8 + q    ]);
                b[1] = __float_as_uint(Bc[nr*36 + kk*8 + q + 4]);
                #pragma unroll
                for (int mi = 0; mi < 4; mi++)
                    mma8(acc[mi][nf], a[mi], b);
            }
        }
    }

    #pragma unroll
    for (int mi = 0; mi < 4; mi++) {
        size_t row0 = (size_t)(mt + wm*64 + mi*16 + g    ) * E_D + nt;
        size_t row1 = (size_t)(mt + wm*64 + mi*16 + g + 8) * E_D + nt;
        #pragma unroll
        for (int nf = 0; nf < 8; nf++) {
            int c = wn*64 + nf*8 + 2*q;
            float2 bb = *(const float2*)&bo[nt + c];
            *(float2*)&out[row0 + c] =
                make_float2(acc[mi][nf][0] + bb.x, acc[mi][nf][1] + bb.y);
            *(float2*)&out[row1 + c] =
                make_float2(acc[mi][nf][2] + bb.x, acc[mi][nf][3] + bb.y);
        }
    }
}

// ============================================================================
extern "C" void kernel_launch(void* const* d_in, const int* in_sizes, int n_in,
                              void* d_out, int out_size)
{
    const float* values = (const float*)d_in[0];
    const float* keysp  = (const float*)d_in[1];
    const float* query  = (const float*)d_in[2];
    const int*   mask   = (const int*)  d_in[3];
    const float* Wv     = (const float*)d_in[4];
    const float* Wk     = (const float*)d_in[5];
    const float* Wq     = (const float*)d_in[6];
    const float* Wo     = (const float*)d_in[7];
    const float* bo     = (const float*)d_in[8];
    float* out = (float*)d_out;

    // 0. pre-round weights to TF32
    cvt_wqkv_kernel<<<12, 256>>>(Wq, Wk, Wv);
    cvt_wo_kernel<<<E_D*E_D/4/256, 256>>>(Wo);

    // 1. QKV projections (W in registers, X pipelined)
    proj_mma<<<dim3((N_B*L_S*H_N)/256, 3), 256>>>(values, keysp, query);

    // 2. flash attention (~104 KB dynamic smem)
    int smem_attn = (2*64*KSTR + 2*64*VSTR + 128*PSTR) * (int)sizeof(float);
    cudaFuncSetAttribute(attn_mma,
                         cudaFuncAttributeMaxDynamicSharedMemorySize, smem_attn);
    attn_mma<<<dim3(L_S/128, H_N, N_B), 128, smem_attn>>>(mask);

    // 3. output projection + bias (72 KB dynamic smem)
    int smem_og = 4*128*36 * (int)sizeof(float);
    cudaFuncSetAttribute(out_gemm_mma,
                         cudaFuncAttributeMaxDynamicSharedMemorySize, smem_og);
    out_gemm_mma<<<dim3(E_D/128, (N_B*L_S)/128), 128, smem_og>>>(bo, out);
}

// round 6
// speedup vs baseline: 3.9888x; 1.0222x over previous
#include <cuda_runtime.h>
#include <cstdint>
#include <cstddef>

#define N_B 2
#define L_S 2048
#define E_D 1024
#define H_N 16
#define D_H 64
#define L2E 1.44269504088896341f

// -------- scratch (device globals; no allocations allowed) --------
// All hold TF32-pre-rounded values. g_q is additionally pre-scaled by 1/32.
__device__ float g_q [N_B*H_N*L_S*D_H];   // [n][h][l][d]
__device__ float g_k [N_B*H_N*L_S*D_H];
__device__ float g_v [N_B*H_N*L_S*D_H];   // [n][h][l][d]
__device__ float g_vt[N_B*H_N*L_S*D_H];   // [n][h][d][l]  (transposed V)
__device__ float g_ao[N_B*L_S*E_D];       // attention output [n*L+l][E]
__device__ float g_wo[E_D*E_D];           // Wo, TF32-rounded
__device__ float g_wq[D_H*D_H];
__device__ float g_wk[D_H*D_H];
__device__ float g_wv[D_H*D_H];
__device__ float g_mb[N_B*L_S];           // mask bias: 0 or -1e30

// ---------------- helpers ----------------
__device__ __forceinline__ uint32_t f2tf(float f) {
    uint32_t u; asm("cvt.rna.tf32.f32 %0, %1;" : "=r"(u) : "f"(f)); return u;
}
__device__ __forceinline__ float f2tf_f(float f) { return __uint_as_float(f2tf(f)); }
__device__ __forceinline__ float ex2(float x) {
    float y; asm("ex2.approx.f32 %0, %1;" : "=f"(y) : "f"(x)); return y;
}
__device__ __forceinline__ void mma8(float* d, const uint32_t* a, const uint32_t* b) {
    asm("mma.sync.aligned.m16n8k8.row.col.f32.tf32.tf32.f32 "
        "{%0,%1,%2,%3},{%4,%5,%6,%7},{%8,%9},{%0,%1,%2,%3};"
        : "+f"(d[0]), "+f"(d[1]), "+f"(d[2]), "+f"(d[3])
        : "r"(a[0]), "r"(a[1]), "r"(a[2]), "r"(a[3]),
          "r"(b[0]), "r"(b[1]));
}
__device__ __forceinline__ void ldsm4(uint32_t* r, uint32_t addr) {
    asm volatile("ldmatrix.sync.aligned.m8n8.x4.shared.b16 {%0,%1,%2,%3}, [%4];"
        : "=r"(r[0]), "=r"(r[1]), "=r"(r[2]), "=r"(r[3]) : "r"(addr));
}
__device__ __forceinline__ void cp16(uint32_t dst, const void* src) {
    asm volatile("cp.async.ca.shared.global [%0], [%1], 16;" :: "r"(dst), "l"(src));
}
#define CP_COMMIT() asm volatile("cp.async.commit_group;")
#define CP_WAIT0()  asm volatile("cp.async.wait_group 0;")
// tf32 m16n8k8 fragment quad layout (g=lane>>2, q=lane&3):
//  A: a0=(g,q) a1=(g+8,q) a2=(g,q+4) a3=(g+8,q+4)
//  B: b0=(k=q,n=g) b1=(k=q+4,n=g)
//  C: c0=(g,2q) c1=(g,2q+1) c2=(g+8,2q) c3=(g+8,2q+1)
// ldmatrix.m8n8.b16 on an 8-row x 16B tile of b32 gives lane -> (row=lane>>2,
// col=lane&3), matching both A and B quad layouts.
// LDSM x4 lane->address bases:
//  B-type (K/V): row=(l>>4)*8+(l&7), coloff=((l>>3)&1)*4 -> r0,r1 = b0,b1 of
//                first 8 n-rows; r2,r3 = next 8 n-rows.
//  A-type (P/Q): row=((l>>3)&1)*8+(l&7), coloff=(l>>4)*4 -> r0..r3 = a0..a3.

// ============================================================================
// Kernel 0a: TF32 rounding of Wo
// ============================================================================
__global__ __launch_bounds__(256) void cvt_wo_kernel(const float* __restrict__ Wo)
{
    int i = blockIdx.x * 256 + threadIdx.x;
    float4 v = ((const float4*)Wo)[i];
    v.x = f2tf_f(v.x); v.y = f2tf_f(v.y); v.z = f2tf_f(v.z); v.w = f2tf_f(v.w);
    ((float4*)g_wo)[i] = v;
}

// Kernel 0b: TF32 rounding of Wq/Wk/Wv
__global__ __launch_bounds__(256) void cvt_wqkv_kernel(
    const float* __restrict__ Wq, const float* __restrict__ Wk,
    const float* __restrict__ Wv)
{
    int i = blockIdx.x * 256 + threadIdx.x;   // 0..3071
    int which = i >> 10, j = i & 1023;
    const float4* src = (const float4*)(which == 0 ? Wq : (which == 1 ? Wk : Wv));
    float4* dst = (float4*)(which == 0 ? g_wq : (which == 1 ? g_wk : g_wv));
    float4 v = src[j];
    v.x = f2tf_f(v.x); v.y = f2tf_f(v.y); v.z = f2tf_f(v.z); v.w = f2tf_f(v.w);
    dst[j] = v;
}

// Kernel 0c: mask -> additive bias floats
__global__ __launch_bounds__(256) void mask_bias_kernel(const int* __restrict__ mask)
{
    int i = blockIdx.x * 256 + threadIdx.x;   // 0..4095
    g_mb[i] = mask[i] ? 0.f : -1.0e30f;
}

// ============================================================================
// Kernel 1: QKV projection. 256 rows/block, 256 threads (8 warps = 4m x 2n).
// W fragments in registers; X pipelined cp.async. Q output pre-scaled by 1/32.
// ============================================================================
__global__ __launch_bounds__(256) void proj_mma(
    const float* __restrict__ vals, const float* __restrict__ keys,
    const float* __restrict__ qry)
{
    const float* X; const float* Wc; float* Y; float oscale;
    int which = blockIdx.y;
    if (which == 0)      { X = vals; Wc = g_wv; Y = g_v; oscale = 1.f; }
    else if (which == 1) { X = keys; Wc = g_wk; Y = g_k; oscale = 1.f; }
    else                 { X = qry;  Wc = g_wq; Y = g_q; oscale = 0.03125f; }

    __shared__ float Xs[2][64*68];

    int rowBase0 = blockIdx.x * 256;
    int tid = threadIdx.x, warp = tid >> 5, lane = tid & 31;
    int g = lane >> 2, q = lane & 3;
    int wm = warp & 3, wn = warp >> 2;

    uint32_t wb[8][4][2];
    #pragma unroll
    for (int kk = 0; kk < 8; kk++)
        #pragma unroll
        for (int nf2 = 0; nf2 < 4; nf2++) {
            int nn = wn*32 + nf2*8 + g;
            wb[kk][nf2][0] = __float_as_uint(__ldg(&Wc[nn*64 + kk*8 + q    ]));
            wb[kk][nf2][1] = __float_as_uint(__ldg(&Wc[nn*64 + kk*8 + q + 4]));
        }

    uint32_t xs_u = (uint32_t)__cvta_generic_to_shared(Xs);

    {
        const float4* Xg = (const float4*)(X + (size_t)rowBase0 * 64);
        for (int i = tid; i < 1024; i += 256) {
            int r = i >> 4, c4 = (i & 15) << 2;
            cp16(xs_u + (r*68 + c4)*4, Xg + i);
        }
        CP_COMMIT();
    }

    for (int rt = 0; rt < 4; rt++) {
        CP_WAIT0();
        __syncthreads();

        if (rt + 1 < 4) {
            const float4* Xg = (const float4*)(X + (size_t)(rowBase0 + (rt+1)*64) * 64);
            uint32_t xo = xs_u + ((rt+1)&1) * 64*68*4;
            for (int i = tid; i < 1024; i += 256) {
                int r = i >> 4, c4 = (i & 15) << 2;
                cp16(xo + (r*68 + c4)*4, Xg + i);
            }
            CP_COMMIT();
        }
        const float* Xc = Xs[rt & 1];

        float acc[4][4];
        #pragma unroll
        for (int nf2 = 0; nf2 < 4; nf2++)
            #pragma unroll
            for (int t = 0; t < 4; t++) acc[nf2][t] = 0.f;

        #pragma unroll
        for (int kk = 0; kk < 8; kk++) {
            uint32_t a[4];
            a[0] = f2tf(Xc[(wm*16+g  )*68 + kk*8 + q    ]);
            a[1] = f2tf(Xc[(wm*16+g+8)*68 + kk*8 + q    ]);
            a[2] = f2tf(Xc[(wm*16+g  )*68 + kk*8 + q + 4]);
            a[3] = f2tf(Xc[(wm*16+g+8)*68 + kk*8 + q + 4]);
            #pragma unroll
            for (int nf2 = 0; nf2 < 4; nf2++)
                mma8(acc[nf2], a, wb[kk][nf2]);
        }

        int r0 = rowBase0 + rt*64 + wm*16 + g;
        int r1 = r0 + 8;
        int h0 = r0 & 15, nl0 = r0 >> 4;
        int h1 = r1 & 15, nl1 = r1 >> 4;
        size_t base0 = (((size_t)((nl0 >> 11)*H_N + h0))*L_S + (nl0 & (L_S-1)))*D_H;
        size_t base1 = (((size_t)((nl1 >> 11)*H_N + h1))*L_S + (nl1 & (L_S-1)))*D_H;
        #pragma unroll
        for (int nf2 = 0; nf2 < 4; nf2++) {
            int c = wn*32 + nf2*8 + 2*q;
            *(float2*)&Y[base0 + c] =
                make_float2(f2tf_f(acc[nf2][0]*oscale), f2tf_f(acc[nf2][1]*oscale));
            *(float2*)&Y[base1 + c] =
                make_float2(f2tf_f(acc[nf2][2]*oscale), f2tf_f(acc[nf2][3]*oscale));
        }
    }
}

// ============================================================================
// Kernel 1b: transpose V per head: [l][d] -> [d][l]
// ============================================================================
__global__ __launch_bounds__(256) void transpose_v_kernel()
{
    __shared__ float ts[64][65];
    int lt = blockIdx.x * 64;   // l-tile
    int nh = blockIdx.y;
    int tid = threadIdx.x;

    const float* src = g_v + (size_t)nh * L_S * D_H + (size_t)lt * D_H;  // [l][d]
    for (int i = tid; i < 1024; i += 256) {
        int r = i >> 4, c4 = (i & 15) << 2;
        float4 v = *(const float4*)&src[r*64 + c4];
        ts[r][c4+0] = v.x; ts[r][c4+1] = v.y; ts[r][c4+2] = v.z; ts[r][c4+3] = v.w;
    }
    __syncthreads();

    float* dst = g_vt + (size_t)nh * L_S * D_H;   // [d][l]
    for (int i = tid; i < 1024; i += 256) {
        int d = i >> 4, l4 = (i & 15) << 2;
        float4 o;
        o.x = ts[l4+0][d]; o.y = ts[l4+1][d]; o.z = ts[l4+2][d]; o.w = ts[l4+3][d];
        *(float4*)&dst[(size_t)d * L_S + lt + l4] = o;
    }
}

// ============================================================================
// Kernel 2: flash attention. q-tile 128, 128 threads (4 warps, m32 strips).
// All fragments via ldmatrix; register softmax; double-buffered K/V cp.async.
// ============================================================================
#define KSTR 68
#define VSTR 68
#define PSTR 68

__global__ __launch_bounds__(128) void attn_mma()
{
    extern __shared__ float sm[];
    float* Ksb = sm;                    // [2][64*KSTR]  K: [c][e]
    float* Vsb = sm + 2*64*KSTR;        // [2][64*VSTR]  Vt: [d][c]
    float* Ps  = Vsb + 2*64*VSTR;       // [128*PSTR]    P/Q: [r][c]

    int qt = blockIdx.x, h = blockIdx.y, n = blockIdx.z;
    int tid = threadIdx.x, warp = tid >> 5, lane = tid & 31;
    int g = lane >> 2, q = lane & 3;
    int m0 = warp * 32;

    const float* Qg  = g_q  + ((size_t)(n*H_N + h) * L_S + qt*128) * D_H;
    const float* Kg  = g_k  +  (size_t)(n*H_N + h) * L_S * D_H;
    const float* Vtg = g_vt +  (size_t)(n*H_N + h) * L_S * D_H;
    const float* mb  = g_mb + n * L_S;

    uint32_t ks_u = (uint32_t)__cvta_generic_to_shared(Ksb);
    uint32_t vs_u = (uint32_t)__cvta_generic_to_shared(Vsb);
    uint32_t ps_u = (uint32_t)__cvta_generic_to_shared(Ps);

    // ldmatrix per-lane address bases
    uint32_t bB = ((lane>>4)*8 + (lane&7));          // B-type row in 16-row group
    uint32_t bBc = ((lane>>3)&1)*4;                  // B-type col offset
    uint32_t addrK = ks_u + (bB*KSTR + bBc)*4;
    uint32_t addrV = vs_u + (bB*VSTR + bBc)*4;
    uint32_t aA = (((lane>>3)&1)*8 + (lane&7));      // A-type row
    uint32_t aAc = (lane>>4)*4;                      // A-type col offset
    uint32_t addrP = ps_u + (aA*PSTR + aAc)*4;

    // prefetch K/V tile 0
    {
        const float4* K4 = (const float4*)Kg;
        for (int i = tid; i < 1024; i += 128) {
            int r = i >> 4, c4 = (i & 15) << 2;
            cp16(ks_u + (r*KSTR + c4)*4, K4 + i);
            cp16(vs_u + (r*VSTR + c4)*4, &Vtg[(size_t)r * L_S + c4]);
        }
        CP_COMMIT();
    }

    // stage Q (128x64, pre-scaled by 1/32) into Ps
    for (int i = tid; i < 2048; i += 128) {
        int r = i >> 4, c4 = (i & 15) << 2;
        *(float4*)&Ps[r*PSTR + c4] = ((const float4*)Qg)[i];
    }
    __syncthreads();

    uint32_t qa[2][8][4];
    #pragma unroll
    for (int mi = 0; mi < 2; mi++)
        #pragma unroll
        for (int kk = 0; kk < 8; kk++)
            ldsm4(qa[mi][kk], addrP + (((m0 + mi*16)*PSTR + kk*8) << 2));

    float O[2][8][4];
    #pragma unroll
    for (int mi = 0; mi < 2; mi++)
        #pragma unroll
        for (int nf = 0; nf < 8; nf++)
            #pragma unroll
            for (int t = 0; t < 4; t++) O[mi][nf][t] = 0.f;
    float mrow[2][2] = {{-3.0e38f,-3.0e38f},{-3.0e38f,-3.0e38f}};
    float lrow[2][2] = {{0.f,0.f},{0.f,0.f}};

    for (int kt = 0; kt < L_S/64; kt++) {
        CP_WAIT0();
        __syncthreads();          // tile kt visible; prev buffer free

        if (kt + 1 < L_S/64) {
            const float4* K4 = (const float4*)(Kg + (size_t)(kt+1) * 4096);
            uint32_t ko = ks_u + ((kt+1)&1) * 64*KSTR*4;
            uint32_t vo = vs_u + ((kt+1)&1) * 64*VSTR*4;
            for (int i = tid; i < 1024; i += 128) {
                int r = i >> 4, c4 = (i & 15) << 2;
                cp16(ko + (r*KSTR + c4)*4, K4 + i);
                cp16(vo + (r*VSTR + c4)*4, &Vtg[(size_t)r * L_S + (kt+1)*64 + c4]);
            }
            CP_COMMIT();
        }
        uint32_t kbuf = addrK + (kt&1) * 64*KSTR*4;
        uint32_t vbuf = addrV + (kt&1) * 64*VSTR*4;

        // ---- S = Q K^T ----
        float sacc[2][8][4];
        #pragma unroll
        for (int mi = 0; mi < 2; mi++)
            #pragma unroll
            for (int nf = 0; nf < 8; nf++)
                #pragma unroll
                for (int t = 0; t < 4; t++) sacc[mi][nf][t] = 0.f;

        #pragma unroll
        for (int kk = 0; kk < 8; kk++) {
            #pragma unroll
            for (int nfp = 0; nfp < 4; nfp++) {
                uint32_t kb[4];
                ldsm4(kb, kbuf + ((nfp*16*KSTR + kk*8) << 2));
                mma8(sacc[0][2*nfp  ], qa[0][kk], kb    );
                mma8(sacc[1][2*nfp  ], qa[1][kk], kb    );
                mma8(sacc[0][2*nfp+1], qa[0][kk], kb + 2);
                mma8(sacc[1][2*nfp+1], qa[1][kk], kb + 2);
            }
        }

        // ---- mask bias + row max (Q pre-scaled; pure adds) ----
        float rmax[2][2] = {{-3.0e38f,-3.0e38f},{-3.0e38f,-3.0e38f}};
        #pragma unroll
        for (int nf = 0; nf < 8; nf++) {
            float2 m2 = *(const float2*)&mb[kt*64 + nf*8 + 2*q];
            #pragma unroll
            for (int mi = 0; mi < 2; mi++) {
                float s0 = sacc[mi][nf][0] + m2.x;
                float s1 = sacc[mi][nf][1] + m2.y;
                float s2 = sacc[mi][nf][2] + m2.x;
                float s3 = sacc[mi][nf][3] + m2.y;
                sacc[mi][nf][0]=s0; sacc[mi][nf][1]=s1;
                sacc[mi][nf][2]=s2; sacc[mi][nf][3]=s3;
                rmax[mi][0] = fmaxf(rmax[mi][0], fmaxf(s0, s1));
                rmax[mi][1] = fmaxf(rmax[mi][1], fmaxf(s2, s3));
            }
        }
        float mnew[2][2], cr[2][2];
        #pragma unroll
        for (int mi = 0; mi < 2; mi++)
            #pragma unroll
            for (int hf = 0; hf < 2; hf++) {
                float v = rmax[mi][hf];
                v = fmaxf(v, __shfl_xor_sync(0xffffffffu, v, 1));
                v = fmaxf(v, __shfl_xor_sync(0xffffffffu, v, 2));
                mnew[mi][hf] = fmaxf(mrow[mi][hf], v);
                cr[mi][hf]   = ex2((mrow[mi][hf] - mnew[mi][hf]) * L2E);
            }

        // ---- exp + P store (TF32-rounded) + row sum ----
        float psum[2][2] = {{0.f,0.f},{0.f,0.f}};
        #pragma unroll
        for (int nf = 0; nf < 8; nf++) {
            int c = nf*8 + 2*q;
            #pragma unroll
            for (int mi = 0; mi < 2; mi++) {
                float p0 = ex2((sacc[mi][nf][0] - mnew[mi][0]) * L2E);
                float p1 = ex2((sacc[mi][nf][1] - mnew[mi][0]) * L2E);
                float p2 = ex2((sacc[mi][nf][2] - mnew[mi][1]) * L2E);
                float p3 = ex2((sacc[mi][nf][3] - mnew[mi][1]) * L2E);
                psum[mi][0] += p0 + p1;
                psum[mi][1] += p2 + p3;
                int mr = m0 + mi*16;
                *(float2*)&Ps[(mr+g  )*PSTR + c] = make_float2(f2tf_f(p0), f2tf_f(p1));
                *(float2*)&Ps[(mr+g+8)*PSTR + c] = make_float2(f2tf_f(p2), f2tf_f(p3));
            }
        }
        #pragma unroll
        for (int mi = 0; mi < 2; mi++)
            #pragma unroll
            for (int hf = 0; hf < 2; hf++) {
                float v = psum[mi][hf];
                v += __shfl_xor_sync(0xffffffffu, v, 1);
                v += __shfl_xor_sync(0xffffffffu, v, 2);
                lrow[mi][hf] = lrow[mi][hf] * cr[mi][hf] + v;
                mrow[mi][hf] = mnew[mi][hf];
            }

        #pragma unroll
        for (int mi = 0; mi < 2; mi++)
            #pragma unroll
            for (int nf = 0; nf < 8; nf++) {
                O[mi][nf][0] *= cr[mi][0]; O[mi][nf][1] *= cr[mi][0];
                O[mi][nf][2] *= cr[mi][1]; O[mi][nf][3] *= cr[mi][1];
            }
        __syncwarp();   // P strip visible within warp (ldmatrix crosses lanes)

        // ---- O += P @ V ----
        #pragma unroll
        for (int ck = 0; ck < 8; ck++) {
            uint32_t pa[2][4];
            ldsm4(pa[0], addrP + (((m0     )*PSTR + ck*8) << 2));
            ldsm4(pa[1], addrP + (((m0 + 16)*PSTR + ck*8) << 2));
            #pragma unroll
            for (int nfp = 0; nfp < 4; nfp++) {
                uint32_t vb[4];
                ldsm4(vb, vbuf + ((nfp*16*VSTR + ck*8) << 2));
                mma8(O[0][2*nfp  ], pa[0], vb    );
                mma8(O[1][2*nfp  ], pa[1], vb    );
                mma8(O[0][2*nfp+1], pa[0], vb + 2);
                mma8(O[1][2*nfp+1], pa[1], vb + 2);
            }
        }
    }

    // ---- epilogue ----
    #pragma unroll
    for (int mi = 0; mi < 2; mi++) {
        float invl0 = 1.0f / lrow[mi][0];
        float invl1 = 1.0f / lrow[mi][1];
        size_t row0 = ((size_t)n*L_S + qt*128 + m0 + mi*16 + g    ) * E_D + h*D_H;
        size_t row1 = ((size_t)n*L_S + qt*128 + m0 + mi*16 + g + 8) * E_D + h*D_H;
        #pragma unroll
        for (int nf = 0; nf < 8; nf++) {
            int c = nf*8 + 2*q;
            *(float2*)&g_ao[row0 + c] =
                make_float2(f2tf_f(O[mi][nf][0]*invl0), f2tf_f(O[mi][nf][1]*invl0));
            *(float2*)&g_ao[row1 + c] =
                make_float2(f2tf_f(O[mi][nf][2]*invl1), f2tf_f(O[mi][nf][3]*invl1));
        }
    }
}

// ============================================================================
// Kernel 3: out = A @ Wo^T + bo. 128x128 tile, BK=32, 128 threads
// (4 warps = 2m x 2n, m64 x n64 warp tile). ldmatrix fragment loads.
// ============================================================================
__global__ __launch_bounds__(128) void out_gemm_mma(
    const float* __restrict__ bo, float* __restrict__ out)
{
    extern __shared__ float sm[];
    float* As = sm;              // [2][128*36]
    float* Bs = sm + 2*128*36;   // [2][128*36]

    int nt = blockIdx.x * 128;
    int mt = blockIdx.y * 128;
    int tid = threadIdx.x, warp = tid >> 5, lane = tid & 31;
    int g = lane >> 2, q = lane & 3;
    int wm = warp & 1, wn = warp >> 1;

    uint32_t as_u = (uint32_t)__cvta_generic_to_shared(As);
    uint32_t bs_u = (uint32_t)__cvta_generic_to_shared(Bs);

    uint32_t aA = (((lane>>3)&1)*8 + (lane&7));
    uint32_t aAc = (lane>>4)*4;
    uint32_t addrA = as_u + ((aA*36 + aAc) << 2);
    uint32_t bB = ((lane>>4)*8 + (lane&7));
    uint32_t bBc = ((lane>>3)&1)*4;
    uint32_t addrB = bs_u + ((bB*36 + bBc) << 2);

    float acc[4][8][4];
    #pragma unroll
    for (int mi = 0; mi < 4; mi++)
        #pragma unroll
        for (int nf = 0; nf < 8; nf++)
            #pragma unroll
            for (int t = 0; t < 4; t++) acc[mi][nf][t] = 0.f;

    for (int i = tid; i < 2048; i += 128) {
        int i2 = i & 1023;
        int r = i2 >> 3, c4 = (i2 & 7) << 2;
        if (i < 1024) cp16(as_u + (r*36 + c4)*4, &g_ao[(size_t)(mt + r)*E_D + c4]);
        else          cp16(bs_u + (r*36 + c4)*4, &g_wo[(size_t)(nt + r)*E_D + c4]);
    }
    CP_COMMIT();

    for (int t = 0; t < E_D/32; t++) {
        CP_WAIT0();
        __syncthreads();

        if (t + 1 < E_D/32) {
            int kt = (t + 1) * 32;
            uint32_t ao  = as_u + ((t+1)&1) * 128*36*4;
            uint32_t bou = bs_u + ((t+1)&1) * 128*36*4;
            for (int i = tid; i < 2048; i += 128) {
                int i2 = i & 1023;
                int r = i2 >> 3, c4 = (i2 & 7) << 2;
                if (i < 1024) cp16(ao  + (r*36 + c4)*4, &g_ao[(size_t)(mt + r)*E_D + kt + c4]);
                else          cp16(bou + (r*36 + c4)*4, &g_wo[(size_t)(nt + r)*E_D + kt + c4]);
            }
            CP_COMMIT();
        }
        uint32_t abuf = addrA + (t&1) * 128*36*4;
        uint32_t bbuf = addrB + (t&1) * 128*36*4;

        #pragma unroll
        for (int kk = 0; kk < 4; kk++) {
            uint32_t a[4][4];
            #pragma unroll
            for (int mi = 0; mi < 4; mi++)
                ldsm4(a[mi], abuf + (((wm*64 + mi*16)*36 + kk*8) << 2));
            #pragma unroll
            for (int nfp = 0; nfp < 4; nfp++) {
                uint32_t b[4];
                ldsm4(b, bbuf + (((wn*64 + nfp*16)*36 + kk*8) << 2));
                #pragma unroll
                for (int mi = 0; mi < 4; mi++) {
                    mma8(acc[mi][2*nfp  ], a[mi], b    );
                    mma8(acc[mi][2*nfp+1], a[mi], b + 2);
                }
            }
        }
    }

    #pragma unroll
    for (int mi = 0; mi < 4; mi++) {
        size_t row0 = (size_t)(mt + wm*64 + mi*16 + g    ) * E_D + nt;
        size_t row1 = (size_t)(mt + wm*64 + mi*16 + g + 8) * E_D + nt;
        #pragma unroll
        for (int nf = 0; nf < 8; nf++) {
            int c = wn*64 + nf*8 + 2*q;
            float2 bb = *(const float2*)&bo[nt + c];
            *(float2*)&out[row0 + c] =
                make_float2(acc[mi][nf][0] + bb.x, acc[mi][nf][1] + bb.y);
            *(float2*)&out[row1 + c] =
                make_float2(acc[mi][nf][2] + bb.x, acc[mi][nf][3] + bb.y);
        }
    }
}

// ============================================================================
extern "C" void kernel_launch(void* const* d_in, const int* in_sizes, int n_in,
                              void* d_out, int out_size)
{
    const float* values = (const float*)d_in[0];
    const float* keysp  = (const float*)d_in[1];
    const float* query  = (const float*)d_in[2];
    const int*   mask   = (const int*)  d_in[3];
    const float* Wv     = (const float*)d_in[4];
    const float* Wk     = (const float*)d_in[5];
    const float* Wq     = (const float*)d_in[6];
    const float* Wo     = (const float*)d_in[7];
    const float* bo     = (const float*)d_in[8];
    float* out = (float*)d_out;

    // 0. pre-round weights; mask -> bias
    cvt_wqkv_kernel<<<12, 256>>>(Wq, Wk, Wv);
    mask_bias_kernel<<<N_B*L_S/256, 256>>>(mask);
    cvt_wo_kernel<<<E_D*E_D/4/256, 256>>>(Wo);

    // 1. QKV projections (+ Q pre-scale), then V transpose
    proj_mma<<<dim3((N_B*L_S*H_N)/256, 3), 256>>>(values, keysp, query);
    transpose_v_kernel<<<dim3(L_S/64, N_B*H_N), 256>>>();

    // 2. flash attention (~102 KB dynamic smem)
    int smem_attn = (2*64*KSTR + 2*64*VSTR + 128*PSTR) * (int)sizeof(float);
    cudaFuncSetAttribute(attn_mma,
                         cudaFuncAttributeMaxDynamicSharedMemorySize, smem_attn);
    attn_mma<<<dim3(L_S/128, H_N, N_B), 128, smem_attn>>>();

    // 3. output projection + bias (72 KB dynamic smem)
    int smem_og = 4*128*36 * (int)sizeof(float);
    cudaFuncSetAttribute(out_gemm_mma,
                         cudaFuncAttributeMaxDynamicSharedMemorySize, smem_og);
    out_gemm_mma<<<dim3(E_D/128, (N_B*L_S)/128), 128, smem_og>>>(bo, out);
}